// round 2
// baseline (speedup 1.0000x reference)
#include <cuda_runtime.h>
#include <math.h>

#define BB 128
#define TT 512
#define EE 300
#define HH 1024
#define H3 3072
#define KEYLEN 15

// ---------------- device scratch (static allocation; no cudaMalloc) -------------
__device__ float g_xproj[(size_t)BB * TT * H3];  // [t][b][3H]  (805 MB)
__device__ float g_h[2][BB * HH];                // double-buffered hidden state
__device__ float g_kh[HH];                       // key GRU hidden
__device__ float g_khp[H3];                      // key GRU h-projection scratch
__device__ float g_kxp[KEYLEN * H3];             // key GRU input projection
__device__ float g_gate[HH];                     // key gate

__device__ __forceinline__ float sigm(float v) { return 1.f / (1.f + __expf(-v)); }

// ---------------- init: zero h0 and key hidden ----------------------------------
__global__ void zero_kernel() {
    int i = blockIdx.x * blockDim.x + threadIdx.x;
    if (i < BB * HH) g_h[0][i] = 0.f;
    if (i < HH) g_kh[i] = 0.f;
}

// ---------------- xproj: [65536, 3072] = gather(emb, x) @ W_ih^T + b_ih ---------
// Output row i = t*B + b, token = x[b*T + t]. Tile 128x64, K-tile 20 (300 = 15*20).
#define XBM 128
#define XBN 64
#define XBK 20
__global__ void xproj_kernel(const int* __restrict__ x, const float* __restrict__ emb,
                             const float* __restrict__ Wih, const float* __restrict__ bih) {
    __shared__ float As[XBK][XBM + 2];  // [k][row]
    __shared__ float Bs[XBK][XBN];      // [k][col]
    __shared__ int rid[XBM];

    int tid = threadIdx.x;
    int i0 = blockIdx.y * XBM;
    int g0 = blockIdx.x * XBN;

    if (tid < XBM) {
        int i = i0 + tid;
        int t = i / BB, b = i % BB;
        rid[tid] = x[b * TT + t];
    }
    __syncthreads();

    int tx = tid & 15;        // 16 col-threads, 4 cols each
    int ty = tid >> 4;        // 16 row-threads, 8 rows each

    float acc[8][4];
#pragma unroll
    for (int r = 0; r < 8; ++r)
#pragma unroll
        for (int c = 0; c < 4; ++c) acc[r][c] = 0.f;

    for (int k0 = 0; k0 < EE; k0 += XBK) {
        for (int idx = tid; idx < XBM * XBK; idx += 256) {
            int row = idx / XBK, kk = idx % XBK;
            As[kk][row] = emb[(size_t)rid[row] * EE + k0 + kk];
        }
        for (int idx = tid; idx < XBN * XBK; idx += 256) {
            int c = idx / XBK, kk = idx % XBK;
            Bs[kk][c] = Wih[(size_t)(g0 + c) * EE + k0 + kk];
        }
        __syncthreads();
#pragma unroll
        for (int kk = 0; kk < XBK; ++kk) {
            float4 b4 = *reinterpret_cast<const float4*>(&Bs[kk][tx * 4]);
            float bv0 = b4.x, bv1 = b4.y, bv2 = b4.z, bv3 = b4.w;
#pragma unroll
            for (int rr = 0; rr < 8; ++rr) {
                float a = As[kk][ty * 8 + rr];
                acc[rr][0] += a * bv0;
                acc[rr][1] += a * bv1;
                acc[rr][2] += a * bv2;
                acc[rr][3] += a * bv3;
            }
        }
        __syncthreads();
    }
#pragma unroll
    for (int rr = 0; rr < 8; ++rr) {
        size_t i = (size_t)(i0 + ty * 8 + rr);
#pragma unroll
        for (int cc = 0; cc < 4; ++cc) {
            int g = g0 + tx * 4 + cc;
            g_xproj[i * H3 + g] = acc[rr][cc] + bih[g];
        }
    }
}

// ---------------- key GRU: input projection [15, 3072] --------------------------
__global__ void key_xproj_kernel(const int* __restrict__ key_ids, const float* __restrict__ emb,
                                 const float* __restrict__ Wih, const float* __restrict__ bih) {
    __shared__ float ke[KEYLEN][EE];  // 18 KB
    int tid = threadIdx.x;
    for (int idx = tid; idx < KEYLEN * EE; idx += 256) {
        int t = idx / EE, k = idx % EE;
        ke[t][k] = emb[(size_t)key_ids[t] * EE + k];
    }
    __syncthreads();
    int g = blockIdx.x * 256 + tid;
    float acc[KEYLEN];
#pragma unroll
    for (int t = 0; t < KEYLEN; ++t) acc[t] = 0.f;
    const float* w = Wih + (size_t)g * EE;
    for (int k = 0; k < EE; ++k) {
        float wv = w[k];
#pragma unroll
        for (int t = 0; t < KEYLEN; ++t) acc[t] += ke[t][k] * wv;
    }
    float bv = bih[g];
#pragma unroll
    for (int t = 0; t < KEYLEN; ++t) g_kxp[t * H3 + g] = acc[t] + bv;
}

// ---------------- key GRU: hp = W_hh @ kh + b_hh (B=1) --------------------------
__global__ void khp_kernel(const float* __restrict__ Whh, const float* __restrict__ bhh) {
    __shared__ float sh[HH];
    int tid = threadIdx.x;
    for (int i = tid; i < HH; i += 256) sh[i] = g_kh[i];
    __syncthreads();
    int g = blockIdx.x * 256 + tid;
    const float4* w = reinterpret_cast<const float4*>(Whh + (size_t)g * HH);
    float acc = 0.f;
#pragma unroll 4
    for (int k4 = 0; k4 < HH / 4; ++k4) {
        float4 wv = w[k4];
        acc += wv.x * sh[4 * k4] + wv.y * sh[4 * k4 + 1] + wv.z * sh[4 * k4 + 2] + wv.w * sh[4 * k4 + 3];
    }
    g_khp[g] = acc + bhh[g];
}

// ---------------- key GRU: elementwise update (in-place, B=1) -------------------
__global__ void kupdate_kernel(int t) {
    int j = blockIdx.x * 256 + threadIdx.x;
    const float* xp = g_kxp + (size_t)t * H3;
    float r = sigm(xp[j] + g_khp[j]);
    float z = sigm(xp[HH + j] + g_khp[HH + j]);
    float n = tanhf(xp[2 * HH + j] + r * g_khp[2 * HH + j]);
    g_kh[j] = (1.f - z) * n + z * g_kh[j];
}

// ---------------- gate = sigmoid(W_g @ kh + b_g) --------------------------------
__global__ void gate_kernel(const float* __restrict__ Wg, const float* __restrict__ bg) {
    __shared__ float sh[HH];
    int tid = threadIdx.x;
    for (int i = tid; i < HH; i += 256) sh[i] = g_kh[i];
    __syncthreads();
    int j = blockIdx.x * 256 + tid;
    const float4* w = reinterpret_cast<const float4*>(Wg + (size_t)j * HH);
    float acc = 0.f;
#pragma unroll 4
    for (int k4 = 0; k4 < HH / 4; ++k4) {
        float4 wv = w[k4];
        acc += wv.x * sh[4 * k4] + wv.y * sh[4 * k4 + 1] + wv.z * sh[4 * k4 + 2] + wv.w * sh[4 * k4 + 3];
    }
    g_gate[j] = sigm(acc + bg[j]);
}

// ---------------- main recurrence step ------------------------------------------
// Grid: 128 blocks (j-tile = 8 hidden cols, all 3 gates). Block: 128 threads.
// Thread (tx = tid%4, ty = tid/4): cols {j0+tx, j0+tx+4}, rows {ty*4 .. ty*4+3}.
#define KT 32
__global__ void step_kernel(int t, int sel, const float* __restrict__ Whh,
                            const float* __restrict__ bhh, float* __restrict__ ovr) {
    __shared__ float Hs[KT][BB + 2];     // [k][row]
    __shared__ float Ws[3][KT][8];       // [gate][k][col]

    int tid = threadIdx.x;
    int tx = tid & 3;
    int ty = tid >> 2;
    int j0 = blockIdx.x * 8;

    const float* hin = g_h[sel];

    float acc[3][4][2];  // [gate][row][col]
#pragma unroll
    for (int g = 0; g < 3; ++g)
#pragma unroll
        for (int r = 0; r < 4; ++r)
#pragma unroll
            for (int c = 0; c < 2; ++c) acc[g][r][c] = 0.f;

    for (int k0 = 0; k0 < HH; k0 += KT) {
        // load h tile [128 rows x 32 k]
        for (int idx = tid; idx < BB * KT; idx += 128) {
            int row = idx >> 5, kk = idx & 31;
            Hs[kk][row] = hin[row * HH + k0 + kk];
        }
        // load W tile: 24 rows (3 gates x 8 cols) x 32 k
        for (int idx = tid; idx < 24 * KT; idx += 128) {
            int rr = idx >> 5, kk = idx & 31;
            int gg = rr >> 3, c = rr & 7;
            Ws[gg][kk][c] = Whh[(size_t)(gg * HH + j0 + c) * HH + k0 + kk];
        }
        __syncthreads();
#pragma unroll
        for (int kk = 0; kk < KT; ++kk) {
            float w0r = Ws[0][kk][tx], w1r = Ws[0][kk][tx + 4];
            float w0z = Ws[1][kk][tx], w1z = Ws[1][kk][tx + 4];
            float w0n = Ws[2][kk][tx], w1n = Ws[2][kk][tx + 4];
#pragma unroll
            for (int r = 0; r < 4; ++r) {
                float hv = Hs[kk][ty * 4 + r];
                acc[0][r][0] += hv * w0r; acc[0][r][1] += hv * w1r;
                acc[1][r][0] += hv * w0z; acc[1][r][1] += hv * w1z;
                acc[2][r][0] += hv * w0n; acc[2][r][1] += hv * w1n;
            }
        }
        __syncthreads();
    }

    // epilogue: GRU update + key gate
    const float* xp = g_xproj + (size_t)t * BB * H3;
    float* out = ovr ? ovr : g_h[sel ^ 1];
#pragma unroll
    for (int cc = 0; cc < 2; ++cc) {
        int j = j0 + tx + cc * 4;
        float br = bhh[j], bz = bhh[HH + j], bn = bhh[2 * HH + j];
        float gv = g_gate[j];
#pragma unroll
        for (int r = 0; r < 4; ++r) {
            int row = ty * 4 + r;
            const float* xpr = xp + (size_t)row * H3;
            float rg = sigm(xpr[j] + acc[0][r][cc] + br);
            float zg = sigm(xpr[HH + j] + acc[1][r][cc] + bz);
            float ng = tanhf(xpr[2 * HH + j] + rg * (acc[2][r][cc] + bn));
            float hold = hin[row * HH + j];
            out[row * HH + j] = gv * ((1.f - zg) * ng + zg * hold);
        }
    }
}

// ---------------- launch ---------------------------------------------------------
extern "C" void kernel_launch(void* const* d_in, const int* in_sizes, int n_in,
                              void* d_out, int out_size) {
    const int* x        = (const int*)d_in[0];
    const int* key_ids  = (const int*)d_in[1];
    const float* emb    = (const float*)d_in[2];
    const float* W_ih   = (const float*)d_in[3];
    const float* W_hh   = (const float*)d_in[4];
    const float* b_ih   = (const float*)d_in[5];
    const float* b_hh   = (const float*)d_in[6];
    const float* W_g    = (const float*)d_in[7];
    const float* b_g    = (const float*)d_in[8];
    float* out = (float*)d_out;

    zero_kernel<<<(BB * HH + 255) / 256, 256>>>();

    // key GRU phase (tiny)
    key_xproj_kernel<<<H3 / 256, 256>>>(key_ids, emb, W_ih, b_ih);
    for (int t = 0; t < KEYLEN; ++t) {
        khp_kernel<<<H3 / 256, 256>>>(W_hh, b_hh);
        kupdate_kernel<<<HH / 256, 256>>>(t);
    }
    gate_kernel<<<HH / 256, 256>>>(W_g, b_g);

    // input projection for the main sequence
    dim3 xg(H3 / XBN, (BB * TT) / XBM);
    xproj_kernel<<<xg, 256>>>(x, emb, W_ih, b_ih);

    // main recurrence: 512 sequential steps
    for (int t = 0; t < TT; ++t) {
        step_kernel<<<HH / 8, 128>>>(t, t & 1, W_hh, b_hh, (t == TT - 1) ? out : nullptr);
    }
}

// round 5
// speedup vs baseline: 2.3555x; 2.3555x over previous
#include <cuda_runtime.h>
#include <math.h>

#define BB 128
#define TT 512
#define EE 300
#define HH 1024
#define H3 3072
#define KEYLEN 15

#define NBLK 128          // persistent blocks (1 per SM, all resident)
#define NTHR 512
#define KT   64           // k-tile for h staging
#define NKT  (HH / KT)    // 16 tiles
#define WSTR 1026         // W smem stride (floats), bank-spread, 8B-aligned pairs
#define HSTR 68           // Hs smem stride (floats), 16B-aligned rows, bank-spread

typedef unsigned long long ull;

// ---------------- device scratch (static allocation; no cudaMalloc) -------------
__device__ float g_xproj[(size_t)BB * TT * H3];  // [t][b][3H]
__device__ float g_h[2][BB * HH];                // double-buffered hidden state
__device__ float g_kh[HH];                       // key GRU hidden
__device__ float g_khp[H3];                      // key GRU h-projection scratch
__device__ float g_kxp[KEYLEN * H3];             // key GRU input projection
__device__ float g_gate[HH];                     // key gate
__device__ volatile unsigned g_flags[NBLK];      // grid barrier flags

__device__ __forceinline__ float sigm(float v) { return 1.f / (1.f + __expf(-v)); }

__device__ __forceinline__ void ffma2(ull& d, ull a, ull b) {
    asm("fma.rn.f32x2 %0, %1, %2, %0;" : "+l"(d) : "l"(a), "l"(b));
}
__device__ __forceinline__ float hsum2(ull v) {
    return __int_as_float((unsigned)(v & 0xffffffffull)) + __int_as_float((unsigned)(v >> 32));
}

// ---------------- init: zero h0, key hidden, barrier flags ----------------------
__global__ void zero_kernel() {
    int i = blockIdx.x * blockDim.x + threadIdx.x;
    if (i < BB * HH) g_h[0][i] = 0.f;
    if (i < HH) g_kh[i] = 0.f;
    if (i < NBLK) g_flags[i] = 0u;
}

// ---------------- xproj: [65536, 3072] = gather(emb, x) @ W_ih^T + b_ih ---------
// f32x2 k-packed. Tile 128x64, K-tile 20 (10 pairs). 256 threads, 8r x 4c per thread.
#define XBM 128
#define XBN 64
#define XBK 20
__global__ void xproj_kernel(const int* __restrict__ x, const float* __restrict__ emb,
                             const float* __restrict__ Wih, const float* __restrict__ bih) {
    __shared__ float As[XBM * XBK];   // [row][k], stride 20
    __shared__ float Bs[XBN * XBK];   // [col][k], stride 20
    __shared__ int rid[XBM];

    int tid = threadIdx.x;
    int i0 = blockIdx.y * XBM;
    int g0 = blockIdx.x * XBN;

    if (tid < XBM) {
        int i = i0 + tid;
        int t = i / BB, b = i % BB;
        rid[tid] = x[b * TT + t];
    }
    __syncthreads();

    int tx = tid & 15;   // 16 col-groups, 4 cols each
    int ty = tid >> 4;   // 16 row-groups, 8 rows each

    ull acc[8][4];
#pragma unroll
    for (int r = 0; r < 8; ++r)
#pragma unroll
        for (int c = 0; c < 4; ++c) acc[r][c] = 0ull;

    for (int k0 = 0; k0 < EE; k0 += XBK) {
        for (int idx = tid; idx < XBM * XBK; idx += 256) {
            int row = idx / XBK, kk = idx % XBK;
            As[row * XBK + kk] = emb[(size_t)rid[row] * EE + k0 + kk];
        }
        for (int idx = tid; idx < XBN * XBK; idx += 256) {
            int c = idx / XBK, kk = idx % XBK;
            Bs[c * XBK + kk] = Wih[(size_t)(g0 + c) * EE + k0 + kk];
        }
        __syncthreads();
#pragma unroll
        for (int kp = 0; kp < XBK / 2; ++kp) {
            ull bv[4];
#pragma unroll
            for (int c = 0; c < 4; ++c)
                bv[c] = *(const ull*)(Bs + (tx * 4 + c) * XBK + 2 * kp);
#pragma unroll
            for (int r = 0; r < 8; ++r) {
                ull av = *(const ull*)(As + (ty * 8 + r) * XBK + 2 * kp);
#pragma unroll
                for (int c = 0; c < 4; ++c) ffma2(acc[r][c], av, bv[c]);
            }
        }
        __syncthreads();
    }
#pragma unroll
    for (int r = 0; r < 8; ++r) {
        size_t i = (size_t)(i0 + ty * 8 + r);
#pragma unroll
        for (int c = 0; c < 4; ++c) {
            int g = g0 + tx * 4 + c;
            g_xproj[i * H3 + g] = hsum2(acc[r][c]) + bih[g];
        }
    }
}

// ---------------- key GRU: input projection [15, 3072] --------------------------
__global__ void key_xproj_kernel(const int* __restrict__ key_ids, const float* __restrict__ emb,
                                 const float* __restrict__ Wih, const float* __restrict__ bih) {
    __shared__ float ke[KEYLEN][EE];
    int tid = threadIdx.x;
    for (int idx = tid; idx < KEYLEN * EE; idx += 256) {
        int t = idx / EE, k = idx % EE;
        ke[t][k] = emb[(size_t)key_ids[t] * EE + k];
    }
    __syncthreads();
    int g = blockIdx.x * 256 + tid;
    float acc[KEYLEN];
#pragma unroll
    for (int t = 0; t < KEYLEN; ++t) acc[t] = 0.f;
    const float* w = Wih + (size_t)g * EE;
    for (int k = 0; k < EE; ++k) {
        float wv = w[k];
#pragma unroll
        for (int t = 0; t < KEYLEN; ++t) acc[t] += ke[t][k] * wv;
    }
    float bv = bih[g];
#pragma unroll
    for (int t = 0; t < KEYLEN; ++t) g_kxp[t * H3 + g] = acc[t] + bv;
}

// ---------------- key GRU: hp = W_hh @ kh + b_hh (B=1) --------------------------
__global__ void khp_kernel(const float* __restrict__ Whh, const float* __restrict__ bhh) {
    __shared__ float sh[HH];
    int tid = threadIdx.x;
    for (int i = tid; i < HH; i += 256) sh[i] = g_kh[i];
    __syncthreads();
    int g = blockIdx.x * 256 + tid;
    const float4* w = reinterpret_cast<const float4*>(Whh + (size_t)g * HH);
    float acc = 0.f;
#pragma unroll 4
    for (int k4 = 0; k4 < HH / 4; ++k4) {
        float4 wv = w[k4];
        acc += wv.x * sh[4 * k4] + wv.y * sh[4 * k4 + 1] + wv.z * sh[4 * k4 + 2] + wv.w * sh[4 * k4 + 3];
    }
    g_khp[g] = acc + bhh[g];
}

__global__ void kupdate_kernel(int t) {
    int j = blockIdx.x * 256 + threadIdx.x;
    const float* xp = g_kxp + (size_t)t * H3;
    float r = sigm(xp[j] + g_khp[j]);
    float z = sigm(xp[HH + j] + g_khp[HH + j]);
    float n = tanhf(xp[2 * HH + j] + r * g_khp[2 * HH + j]);
    g_kh[j] = (1.f - z) * n + z * g_kh[j];
}

__global__ void gate_kernel(const float* __restrict__ Wg, const float* __restrict__ bg) {
    __shared__ float sh[HH];
    int tid = threadIdx.x;
    for (int i = tid; i < HH; i += 256) sh[i] = g_kh[i];
    __syncthreads();
    int j = blockIdx.x * 256 + tid;
    const float4* w = reinterpret_cast<const float4*>(Wg + (size_t)j * HH);
    float acc = 0.f;
#pragma unroll 4
    for (int k4 = 0; k4 < HH / 4; ++k4) {
        float4 wv = w[k4];
        acc += wv.x * sh[4 * k4] + wv.y * sh[4 * k4 + 1] + wv.z * sh[4 * k4 + 2] + wv.w * sh[4 * k4 + 3];
    }
    g_gate[j] = sigm(acc + bg[j]);
}

// ---------------- persistent recurrence kernel -----------------------------------
// 128 blocks x 512 threads. Block owns 8 hidden cols (x3 gates), W slice cached in
// SMEM for all 512 steps. h streamed via double-buffered cp.async. Grid barrier
// between steps via per-block flags (all blocks resident by construction).

__device__ __forceinline__ void issue_tile(float* hsbuf, const float* hin, int k0, int tid) {
#pragma unroll
    for (int s = 0; s < 4; ++s) {
        int c = tid + s * NTHR;          // 0..2047 chunks of 16B
        int row = c >> 4;                // 16 chunks per row (64 floats)
        int c16 = c & 15;
        unsigned saddr = (unsigned)__cvta_generic_to_shared(hsbuf + row * HSTR + c16 * 4);
        const float* src = hin + row * HH + k0 + c16 * 4;
        asm volatile("cp.async.cg.shared.global [%0], [%1], 16;" :: "r"(saddr), "l"(src));
    }
}

__device__ __forceinline__ void grid_barrier(unsigned target) {
    __syncthreads();
    if (threadIdx.x == 0) {
        __threadfence();
        g_flags[blockIdx.x] = target;
    }
    if (threadIdx.x < NBLK) {
        while (g_flags[threadIdx.x] < target) { }
    }
    __syncthreads();
}

__global__ void __launch_bounds__(NTHR, 1)
recur_kernel(const float* __restrict__ Whh, const float* __restrict__ bhh,
             float* __restrict__ out) {
    extern __shared__ float smem[];
    float* Wsm = smem;                       // 24 * WSTR floats
    float* Hs  = smem + 24 * WSTR;           // 2 * 128 * HSTR floats

    int tid = threadIdx.x;
    int tx = tid & 7;          // j column within block
    int ty = tid >> 3;         // row pair 0..63
    int j0 = blockIdx.x * 8;
    int j  = j0 + tx;
    int r0 = 2 * ty, r1 = r0 + 1;

    // cache W slice: 24 rows (3 gates x 8 cols) x 1024, once for all steps
    for (int idx = tid; idx < 24 * HH; idx += NTHR) {
        int c = idx >> 10, k = idx & (HH - 1);
        int g = c >> 3, cj = c & 7;
        Wsm[c * WSTR + k] = Whh[(size_t)(g * HH + j0 + cj) * HH + k];
    }
    float br = bhh[j], bz = bhh[HH + j], bn = bhh[2 * HH + j];
    float gv = g_gate[j];
    __syncthreads();

#pragma unroll 1
    for (int t = 0; t < TT; ++t) {
        int sel = t & 1;
        const float* hin = g_h[sel];
        float* hout = (t == TT - 1) ? out : g_h[sel ^ 1];
        const float* xp = g_xproj + (size_t)t * BB * H3;

        // independent long-latency prefetches for the epilogue
        float xr0 = __ldcs(xp + (size_t)r0 * H3 + j);
        float xz0 = __ldcs(xp + (size_t)r0 * H3 + HH + j);
        float xn0 = __ldcs(xp + (size_t)r0 * H3 + 2 * HH + j);
        float xr1 = __ldcs(xp + (size_t)r1 * H3 + j);
        float xz1 = __ldcs(xp + (size_t)r1 * H3 + HH + j);
        float xn1 = __ldcs(xp + (size_t)r1 * H3 + 2 * HH + j);
        float hold0 = __ldcg(hin + r0 * HH + j);
        float hold1 = __ldcg(hin + r1 * HH + j);

        issue_tile(Hs, hin, 0, tid);
        asm volatile("cp.async.commit_group;");

        ull ar0 = 0, ar1 = 0, az0 = 0, az1 = 0, an0 = 0, an1 = 0;

#pragma unroll 1
        for (int kt = 0; kt < NKT; ++kt) {
            if (kt + 1 < NKT) {
                issue_tile(Hs + ((kt + 1) & 1) * (BB * HSTR), hin, (kt + 1) * KT, tid);
                asm volatile("cp.async.commit_group;");
                asm volatile("cp.async.wait_group 1;");
            } else {
                asm volatile("cp.async.wait_group 0;");
            }
            __syncthreads();

            const float* hb = Hs + (kt & 1) * (BB * HSTR);
            int k0 = kt * KT;
            const ull* h0p = (const ull*)(hb + r0 * HSTR);
            const ull* h1p = (const ull*)(hb + r1 * HSTR);
            const ull* wr  = (const ull*)(Wsm + (0 + tx)  * WSTR + k0);
            const ull* wz  = (const ull*)(Wsm + (8 + tx)  * WSTR + k0);
            const ull* wn  = (const ull*)(Wsm + (16 + tx) * WSTR + k0);
#pragma unroll
            for (int kk = 0; kk < KT / 2; ++kk) {
                ull h0 = h0p[kk], h1 = h1p[kk];
                ull a = wr[kk]; ffma2(ar0, h0, a); ffma2(ar1, h1, a);
                ull b = wz[kk]; ffma2(az0, h0, b); ffma2(az1, h1, b);
                ull c = wn[kk]; ffma2(an0, h0, c); ffma2(an1, h1, c);
            }
            __syncthreads();
        }

        // epilogue: GRU gates + key gate
        float sr0 = hsum2(ar0), sz0 = hsum2(az0), sn0 = hsum2(an0);
        float sr1 = hsum2(ar1), sz1 = hsum2(az1), sn1 = hsum2(an1);

        float rg0 = sigm(xr0 + sr0 + br);
        float zg0 = sigm(xz0 + sz0 + bz);
        float ng0 = tanhf(xn0 + rg0 * (sn0 + bn));
        hout[r0 * HH + j] = gv * ((1.f - zg0) * ng0 + zg0 * hold0);

        float rg1 = sigm(xr1 + sr1 + br);
        float zg1 = sigm(xz1 + sz1 + bz);
        float ng1 = tanhf(xn1 + rg1 * (sn1 + bn));
        hout[r1 * HH + j] = gv * ((1.f - zg1) * ng1 + zg1 * hold1);

        if (t < TT - 1) grid_barrier((unsigned)(t + 1));
    }
}

// ---------------- launch ---------------------------------------------------------
extern "C" void kernel_launch(void* const* d_in, const int* in_sizes, int n_in,
                              void* d_out, int out_size) {
    const int* x        = (const int*)d_in[0];
    const int* key_ids  = (const int*)d_in[1];
    const float* emb    = (const float*)d_in[2];
    const float* W_ih   = (const float*)d_in[3];
    const float* W_hh   = (const float*)d_in[4];
    const float* b_ih   = (const float*)d_in[5];
    const float* b_hh   = (const float*)d_in[6];
    const float* W_g    = (const float*)d_in[7];
    const float* b_g    = (const float*)d_in[8];
    float* out = (float*)d_out;

    static const int SMEM_BYTES = (24 * WSTR + 2 * BB * HSTR) * 4;  // ~168 KB
    cudaFuncSetAttribute(recur_kernel, cudaFuncAttributeMaxDynamicSharedMemorySize, SMEM_BYTES);

    zero_kernel<<<(BB * HH + 255) / 256, 256>>>();

    // key GRU phase (tiny)
    key_xproj_kernel<<<H3 / 256, 256>>>(key_ids, emb, W_ih, b_ih);
    for (int t = 0; t < KEYLEN; ++t) {
        khp_kernel<<<H3 / 256, 256>>>(W_hh, b_hh);
        kupdate_kernel<<<HH / 256, 256>>>(t);
    }
    gate_kernel<<<HH / 256, 256>>>(W_g, b_g);

    // input projection for the main sequence
    dim3 xg(H3 / XBN, (BB * TT) / XBM);
    xproj_kernel<<<xg, 256>>>(x, emb, W_ih, b_ih);

    // persistent recurrence: all 512 steps in one kernel
    recur_kernel<<<NBLK, NTHR, SMEM_BYTES>>>(W_hh, b_hh, out);
}

// round 9
// speedup vs baseline: 3.5405x; 1.5031x over previous
#include <cuda_runtime.h>
#include <cuda_bf16.h>
#include <math.h>
#include <stdint.h>

#define BB 128
#define TT 512
#define EE 300
#define HH 1024
#define H3 3072
#define KEYLEN 15

#define NBLK 128          // persistent blocks (1 per SM)
#define RTH  256          // recurrence threads (8 warps, one m16-tile each)
#define CHK  64           // K elements per chunk
#define NCH  (HH / CHK)   // 16 chunks per step

// SMEM layout (dynamic, bytes)
#define SM_WHI   0                       // 24 x 1032 bf16 = 49536
#define SM_WLO   49536                   // 49536
#define SM_A     99072                   // 2 stages x 2 arrays x (128 x 72 bf16 = 18432)
#define SM_ASTG  36864
#define SM_AARR  18432
#define SM_BIAS  172800                  // 24 floats
#define SM_GATE  172896                  // 8 floats
#define SM_TOTAL 172928

typedef unsigned long long ull;

// ---------------- device scratch (static; no cudaMalloc) ------------------------
__device__ float g_xproj[(size_t)BB * TT * H3];        // [t][b][3H]
__device__ __nv_bfloat16 g_hhi[2][BB * HH];            // hidden state hi, ping-pong
__device__ __nv_bfloat16 g_hlo[2][BB * HH];            // hidden state lo (residual)
__device__ float g_kh[HH];
__device__ float g_khp[H3];
__device__ float g_kxp[KEYLEN * H3];
__device__ float g_gate[HH];
__device__ volatile unsigned g_flags[NBLK];

__device__ __forceinline__ float sigm(float v) { return 1.f / (1.f + __expf(-v)); }

__device__ __forceinline__ void ffma2(ull& d, ull a, ull b) {
    asm("fma.rn.f32x2 %0, %1, %2, %0;" : "+l"(d) : "l"(a), "l"(b));
}
__device__ __forceinline__ float hsum2(ull v) {
    return __int_as_float((unsigned)(v & 0xffffffffull)) + __int_as_float((unsigned)(v >> 32));
}
__device__ __forceinline__ uint32_t smem_to_u32(const void* p) {
    uint32_t a;
    asm("{ .reg .u64 t; cvta.to.shared.u64 t, %1; cvt.u32.u64 %0, t; }" : "=r"(a) : "l"(p));
    return a;
}

#define LDSM_X4(r0, r1, r2, r3, addr) \
    asm volatile("ldmatrix.sync.aligned.m8n8.x4.shared.b16 {%0,%1,%2,%3}, [%4];" \
                 : "=r"(r0), "=r"(r1), "=r"(r2), "=r"(r3) : "r"(addr))

#define MMA16816(c, a, b0, b1) \
    asm volatile("mma.sync.aligned.m16n8k16.row.col.f32.bf16.bf16.f32 " \
                 "{%0,%1,%2,%3},{%4,%5,%6,%7},{%8,%9},{%0,%1,%2,%3};" \
                 : "+f"((c)[0]), "+f"((c)[1]), "+f"((c)[2]), "+f"((c)[3]) \
                 : "r"((a)[0]), "r"((a)[1]), "r"((a)[2]), "r"((a)[3]), "r"(b0), "r"(b1))

#define CP_ASYNC16(sa, ga) \
    asm volatile("cp.async.cg.shared.global [%0], [%1], 16;" :: "r"(sa), "l"(ga))
#define CP_COMMIT() asm volatile("cp.async.commit_group;")
#define CP_WAIT1()  asm volatile("cp.async.wait_group 1;")
#define CP_WAIT0()  asm volatile("cp.async.wait_group 0;")

// ---------------- init ----------------------------------------------------------
__global__ void zero_kernel() {
    int i = blockIdx.x * blockDim.x + threadIdx.x;
    if (i < BB * HH) {
        g_hhi[0][i] = __float2bfloat16(0.f);
        g_hlo[0][i] = __float2bfloat16(0.f);
    }
    if (i < HH) g_kh[i] = 0.f;
    if (i < NBLK) g_flags[i] = 0u;
}

// ---------------- xproj (f32x2 scalar GEMM, unchanged) --------------------------
#define XBM 128
#define XBN 64
#define XBK 20
__global__ void xproj_kernel(const int* __restrict__ x, const float* __restrict__ emb,
                             const float* __restrict__ Wih, const float* __restrict__ bih) {
    __shared__ float As[XBM * XBK];
    __shared__ float Bs[XBN * XBK];
    __shared__ int rid[XBM];

    int tid = threadIdx.x;
    int i0 = blockIdx.y * XBM;
    int g0 = blockIdx.x * XBN;

    if (tid < XBM) {
        int i = i0 + tid;
        int t = i / BB, b = i % BB;
        rid[tid] = x[b * TT + t];
    }
    __syncthreads();

    int tx = tid & 15;
    int ty = tid >> 4;

    ull acc[8][4];
#pragma unroll
    for (int r = 0; r < 8; ++r)
#pragma unroll
        for (int c = 0; c < 4; ++c) acc[r][c] = 0ull;

    for (int k0 = 0; k0 < EE; k0 += XBK) {
        for (int idx = tid; idx < XBM * XBK; idx += 256) {
            int row = idx / XBK, kk = idx % XBK;
            As[row * XBK + kk] = emb[(size_t)rid[row] * EE + k0 + kk];
        }
        for (int idx = tid; idx < XBN * XBK; idx += 256) {
            int c = idx / XBK, kk = idx % XBK;
            Bs[c * XBK + kk] = Wih[(size_t)(g0 + c) * EE + k0 + kk];
        }
        __syncthreads();
#pragma unroll
        for (int kp = 0; kp < XBK / 2; ++kp) {
            ull bv[4];
#pragma unroll
            for (int c = 0; c < 4; ++c)
                bv[c] = *(const ull*)(Bs + (tx * 4 + c) * XBK + 2 * kp);
#pragma unroll
            for (int r = 0; r < 8; ++r) {
                ull av = *(const ull*)(As + (ty * 8 + r) * XBK + 2 * kp);
#pragma unroll
                for (int c = 0; c < 4; ++c) ffma2(acc[r][c], av, bv[c]);
            }
        }
        __syncthreads();
    }
#pragma unroll
    for (int r = 0; r < 8; ++r) {
        size_t i = (size_t)(i0 + ty * 8 + r);
#pragma unroll
        for (int c = 0; c < 4; ++c) {
            int g = g0 + tx * 4 + c;
            g_xproj[i * H3 + g] = hsum2(acc[r][c]) + bih[g];
        }
    }
}

// ---------------- key GRU phase (unchanged) -------------------------------------
__global__ void key_xproj_kernel(const int* __restrict__ key_ids, const float* __restrict__ emb,
                                 const float* __restrict__ Wih, const float* __restrict__ bih) {
    __shared__ float ke[KEYLEN][EE];
    int tid = threadIdx.x;
    for (int idx = tid; idx < KEYLEN * EE; idx += 256) {
        int t = idx / EE, k = idx % EE;
        ke[t][k] = emb[(size_t)key_ids[t] * EE + k];
    }
    __syncthreads();
    int g = blockIdx.x * 256 + tid;
    float acc[KEYLEN];
#pragma unroll
    for (int t = 0; t < KEYLEN; ++t) acc[t] = 0.f;
    const float* w = Wih + (size_t)g * EE;
    for (int k = 0; k < EE; ++k) {
        float wv = w[k];
#pragma unroll
        for (int t = 0; t < KEYLEN; ++t) acc[t] += ke[t][k] * wv;
    }
    float bv = bih[g];
#pragma unroll
    for (int t = 0; t < KEYLEN; ++t) g_kxp[t * H3 + g] = acc[t] + bv;
}

__global__ void khp_kernel(const float* __restrict__ Whh, const float* __restrict__ bhh) {
    __shared__ float sh[HH];
    int tid = threadIdx.x;
    for (int i = tid; i < HH; i += 256) sh[i] = g_kh[i];
    __syncthreads();
    int g = blockIdx.x * 256 + tid;
    const float4* w = reinterpret_cast<const float4*>(Whh + (size_t)g * HH);
    float acc = 0.f;
#pragma unroll 4
    for (int k4 = 0; k4 < HH / 4; ++k4) {
        float4 wv = w[k4];
        acc += wv.x * sh[4 * k4] + wv.y * sh[4 * k4 + 1] + wv.z * sh[4 * k4 + 2] + wv.w * sh[4 * k4 + 3];
    }
    g_khp[g] = acc + bhh[g];
}

__global__ void kupdate_kernel(int t) {
    int j = blockIdx.x * 256 + threadIdx.x;
    const float* xp = g_kxp + (size_t)t * H3;
    float r = sigm(xp[j] + g_khp[j]);
    float z = sigm(xp[HH + j] + g_khp[HH + j]);
    float n = tanhf(xp[2 * HH + j] + r * g_khp[2 * HH + j]);
    g_kh[j] = (1.f - z) * n + z * g_kh[j];
}

__global__ void gate_kernel(const float* __restrict__ Wg, const float* __restrict__ bg) {
    __shared__ float sh[HH];
    int tid = threadIdx.x;
    for (int i = tid; i < HH; i += 256) sh[i] = g_kh[i];
    __syncthreads();
    int j = blockIdx.x * 256 + tid;
    const float4* w = reinterpret_cast<const float4*>(Wg + (size_t)j * HH);
    float acc = 0.f;
#pragma unroll 4
    for (int k4 = 0; k4 < HH / 4; ++k4) {
        float4 wv = w[k4];
        acc += wv.x * sh[4 * k4] + wv.y * sh[4 * k4 + 1] + wv.z * sh[4 * k4 + 2] + wv.w * sh[4 * k4 + 3];
    }
    g_gate[j] = sigm(acc + bg[j]);
}

// ---------------- grid barrier ---------------------------------------------------
__device__ __forceinline__ void grid_barrier(unsigned target) {
    __syncthreads();
    if (threadIdx.x == 0) {
        __threadfence();
        g_flags[blockIdx.x] = target;
    }
    if (threadIdx.x < NBLK) {
        while (g_flags[threadIdx.x] < target) { }
    }
    __syncthreads();
}

// ---------------- persistent HMMA recurrence -------------------------------------
// 128 blocks x 256 threads (8 warps). Block owns 8 hidden cols x 3 gates = 24 W
// rows (bf16 hi/lo in SMEM, built once). h kept globally as bf16 hi/lo ping-pong,
// streamed per step in 16 double-buffered cp.async chunks of K=64. Each warp owns
// one m16 row-tile; mma.sync m16n8k16 bf16, 3 passes (hh*wh + hh*wl + hl*wh).
__global__ void __launch_bounds__(RTH, 1)
recur_kernel(const float* __restrict__ Whh, const float* __restrict__ bhh,
             float* __restrict__ out) {
    extern __shared__ char smem[];
    uint32_t smem_base = smem_to_u32(smem);
    float* bias_s = (float*)(smem + SM_BIAS);
    float* gate_s = (float*)(smem + SM_GATE);
    __nv_bfloat16* whi_s = (__nv_bfloat16*)(smem + SM_WHI);
    __nv_bfloat16* wlo_s = (__nv_bfloat16*)(smem + SM_WLO);

    int tid = threadIdx.x;
    int lane = tid & 31;
    int w = tid >> 5;
    int j0 = blockIdx.x * 8;

    // Build W_hh hi/lo slice: rows n = gate*8 + cj, k-contiguous, row stride 1032.
    for (int idx = tid; idx < 24 * HH; idx += RTH) {
        int n = idx >> 10, k = idx & (HH - 1);
        float f = Whh[(size_t)((n >> 3) * HH + j0 + (n & 7)) * HH + k];
        __nv_bfloat16 hi = __float2bfloat16_rn(f);
        __nv_bfloat16 lo = __float2bfloat16_rn(f - __bfloat162float(hi));
        whi_s[n * 1032 + k] = hi;
        wlo_s[n * 1032 + k] = lo;
    }
    if (tid < 24) bias_s[tid] = bhh[(tid >> 3) * HH + j0 + (tid & 7)];
    if (tid < 8)  gate_s[tid] = g_gate[j0 + tid];
    __syncthreads();

    // per-thread fragment addresses
    uint32_t a_off = (uint32_t)((16 * w + (lane & 15)) * 144 + (lane >> 4) * 16);
    uint32_t b_off[3];
#pragma unroll
    for (int nt = 0; nt < 3; ++nt)
        b_off[nt] = (uint32_t)((nt * 8 + (lane & 7)) * 2064 + (lane >> 3) * 16);

    int row0 = 16 * w + (lane >> 2);       // epilogue rows row0, row0+8
    int jc = 2 * (lane & 3);               // col pair within 8
    float brv[3], gv = gate_s[jc] , gv1 = gate_s[jc + 1];
#pragma unroll
    for (int nt = 0; nt < 3; ++nt) brv[nt] = 0.f;  // placeholder; biases read per col below
    float b_r0 = bias_s[jc],      b_r1 = bias_s[jc + 1];
    float b_z0 = bias_s[8 + jc],  b_z1 = bias_s[8 + jc + 1];
    float b_n0 = bias_s[16 + jc], b_n1 = bias_s[16 + jc + 1];

#pragma unroll 1
    for (int t = 0; t < TT; ++t) {
        int sel = t & 1;
        const __nv_bfloat16* hhi_in = g_hhi[sel];
        const __nv_bfloat16* hlo_in = g_hlo[sel];
        __nv_bfloat16* hhi_out = g_hhi[sel ^ 1];
        __nv_bfloat16* hlo_out = g_hlo[sel ^ 1];
        const float* xp = g_xproj + (size_t)t * BB * H3;

        // prefetch epilogue inputs (long-latency, independent of MMA)
        const float* xpr0 = xp + (size_t)row0 * H3 + j0 + jc;
        const float* xpr1 = xp + (size_t)(row0 + 8) * H3 + j0 + jc;
        float2 xr0 = __ldcs((const float2*)(xpr0));
        float2 xz0 = __ldcs((const float2*)(xpr0 + HH));
        float2 xn0 = __ldcs((const float2*)(xpr0 + 2 * HH));
        float2 xr1 = __ldcs((const float2*)(xpr1));
        float2 xz1 = __ldcs((const float2*)(xpr1 + HH));
        float2 xn1 = __ldcs((const float2*)(xpr1 + 2 * HH));
        __nv_bfloat162 hh0 = *(const __nv_bfloat162*)(hhi_in + row0 * HH + j0 + jc);
        __nv_bfloat162 hl0 = *(const __nv_bfloat162*)(hlo_in + row0 * HH + j0 + jc);
        __nv_bfloat162 hh1 = *(const __nv_bfloat162*)(hhi_in + (row0 + 8) * HH + j0 + jc);
        __nv_bfloat162 hl1 = *(const __nv_bfloat162*)(hlo_in + (row0 + 8) * HH + j0 + jc);
        float hold00 = __low2float(hh0) + __low2float(hl0);
        float hold01 = __high2float(hh0) + __high2float(hl0);
        float hold10 = __low2float(hh1) + __low2float(hl1);
        float hold11 = __high2float(hh1) + __high2float(hl1);

        float cacc[3][4];
#pragma unroll
        for (int nt = 0; nt < 3; ++nt)
#pragma unroll
            for (int i = 0; i < 4; ++i) cacc[nt][i] = 0.f;

        // prologue: issue chunks 0 and 1
#pragma unroll
        for (int pc = 0; pc < 2; ++pc) {
#pragma unroll
            for (int i = 0; i < 8; ++i) {
                int idx = tid + i * RTH;
                int arr = idx >> 10, rem = idx & 1023;
                int r = rem >> 3, u = rem & 7;
                uint32_t sa = smem_base + SM_A + pc * SM_ASTG + arr * SM_AARR
                              + (uint32_t)(r * 144 + u * 16);
                const char* ga = (const char*)(arr ? hlo_in : hhi_in)
                                 + ((size_t)r * HH + pc * CHK + u * 8) * 2;
                CP_ASYNC16(sa, ga);
            }
            CP_COMMIT();
        }

#pragma unroll 1
        for (int c = 0; c < NCH; ++c) {
            if (c < NCH - 1) { CP_WAIT1(); } else { CP_WAIT0(); }
            __syncthreads();

            uint32_t ab = smem_base + SM_A + (uint32_t)((c & 1) * SM_ASTG) + a_off;
#pragma unroll
            for (int s2 = 0; s2 < 2; ++s2) {
                uint32_t bh[3][4], bl[3][4];
#pragma unroll
                for (int nt = 0; nt < 3; ++nt) {
                    uint32_t bb = smem_base + b_off[nt] + (uint32_t)(c * 128 + s2 * 64);
                    LDSM_X4(bh[nt][0], bh[nt][1], bh[nt][2], bh[nt][3], bb + SM_WHI);
                    LDSM_X4(bl[nt][0], bl[nt][1], bl[nt][2], bl[nt][3], bb + SM_WLO);
                }
#pragma unroll
                for (int s = 0; s < 2; ++s) {
                    uint32_t ah[4], al[4];
                    uint32_t aa = ab + (uint32_t)(s2 * 64 + s * 32);
                    LDSM_X4(ah[0], ah[1], ah[2], ah[3], aa);
                    LDSM_X4(al[0], al[1], al[2], al[3], aa + SM_AARR);
#pragma unroll
                    for (int nt = 0; nt < 3; ++nt) {
                        MMA16816(cacc[nt], ah, bh[nt][2 * s], bh[nt][2 * s + 1]);
                        MMA16816(cacc[nt], ah, bl[nt][2 * s], bl[nt][2 * s + 1]);
                        MMA16816(cacc[nt], al, bh[nt][2 * s], bh[nt][2 * s + 1]);
                    }
                }
            }
            __syncthreads();

            if (c + 2 < NCH) {
                int nc = c + 2;
#pragma unroll
                for (int i = 0; i < 8; ++i) {
                    int idx = tid + i * RTH;
                    int arr = idx >> 10, rem = idx & 1023;
                    int r = rem >> 3, u = rem & 7;
                    uint32_t sa = smem_base + SM_A + (uint32_t)((c & 1) * SM_ASTG)
                                  + arr * SM_AARR + (uint32_t)(r * 144 + u * 16);
                    const char* ga = (const char*)(arr ? hlo_in : hhi_in)
                                     + ((size_t)r * HH + nc * CHK + u * 8) * 2;
                    CP_ASYNC16(sa, ga);
                }
            }
            CP_COMMIT();
        }

        // epilogue: GRU gates + key gate; write hi/lo bf16 (or fp32 out on last step)
#pragma unroll
        for (int half = 0; half < 2; ++half) {
            int row = row0 + half * 8;
            int ib = 2 * half;
            float xr_ = half ? xr1.x : xr0.x, xr_1 = half ? xr1.y : xr0.y;
            float xz_ = half ? xz1.x : xz0.x, xz_1 = half ? xz1.y : xz0.y;
            float xn_ = half ? xn1.x : xn0.x, xn_1 = half ? xn1.y : xn0.y;
            float ho0 = half ? hold10 : hold00;
            float ho1 = half ? hold11 : hold01;

            float rg0 = sigm(xr_ + cacc[0][ib] + b_r0);
            float zg0 = sigm(xz_ + cacc[1][ib] + b_z0);
            float ng0 = tanhf(xn_ + rg0 * (cacc[2][ib] + b_n0));
            float o0 = gv * ((1.f - zg0) * ng0 + zg0 * ho0);

            float rg1 = sigm(xr_1 + cacc[0][ib + 1] + b_r1);
            float zg1 = sigm(xz_1 + cacc[1][ib + 1] + b_z1);
            float ng1 = tanhf(xn_1 + rg1 * (cacc[2][ib + 1] + b_n1));
            float o1 = gv1 * ((1.f - zg1) * ng1 + zg1 * ho1);

            if (t == TT - 1) {
                *(float2*)(out + (size_t)row * HH + j0 + jc) = make_float2(o0, o1);
            } else {
                __nv_bfloat16 h0 = __float2bfloat16_rn(o0);
                __nv_bfloat16 h1 = __float2bfloat16_rn(o1);
                __nv_bfloat162 hv; hv.x = h0; hv.y = h1;
                __nv_bfloat162 lv;
                lv.x = __float2bfloat16_rn(o0 - __bfloat162float(h0));
                lv.y = __float2bfloat16_rn(o1 - __bfloat162float(h1));
                *(__nv_bfloat162*)(hhi_out + (size_t)row * HH + j0 + jc) = hv;
                *(__nv_bfloat162*)(hlo_out + (size_t)row * HH + j0 + jc) = lv;
            }
        }

        if (t < TT - 1) grid_barrier((unsigned)(t + 1));
    }
}

// ---------------- launch ---------------------------------------------------------
extern "C" void kernel_launch(void* const* d_in, const int* in_sizes, int n_in,
                              void* d_out, int out_size) {
    const int* x        = (const int*)d_in[0];
    const int* key_ids  = (const int*)d_in[1];
    const float* emb    = (const float*)d_in[2];
    const float* W_ih   = (const float*)d_in[3];
    const float* W_hh   = (const float*)d_in[4];
    const float* b_ih   = (const float*)d_in[5];
    const float* b_hh   = (const float*)d_in[6];
    const float* W_g    = (const float*)d_in[7];
    const float* b_g    = (const float*)d_in[8];
    float* out = (float*)d_out;

    cudaFuncSetAttribute(recur_kernel, cudaFuncAttributeMaxDynamicSharedMemorySize, SM_TOTAL);

    zero_kernel<<<(BB * HH + 255) / 256, 256>>>();

    // key GRU phase (tiny)
    key_xproj_kernel<<<H3 / 256, 256>>>(key_ids, emb, W_ih, b_ih);
    for (int t = 0; t < KEYLEN; ++t) {
        khp_kernel<<<H3 / 256, 256>>>(W_hh, b_hh);
        kupdate_kernel<<<HH / 256, 256>>>(t);
    }
    gate_kernel<<<HH / 256, 256>>>(W_g, b_g);

    // input projection for the main sequence
    dim3 xg(H3 / XBN, (BB * TT) / XBM);
    xproj_kernel<<<xg, 256>>>(x, emb, W_ih, b_ih);

    // persistent HMMA recurrence: all 512 steps in one kernel
    recur_kernel<<<NBLK, RTH, SM_TOTAL>>>(W_hh, b_hh, out);
}

// round 11
// speedup vs baseline: 3.9962x; 1.1287x over previous
#include <cuda_runtime.h>
#include <cuda_bf16.h>
#include <math.h>
#include <stdint.h>

#define BB 128
#define TT 512
#define EE 300
#define HH 1024
#define H3 3072
#define KEYLEN 15

#define NBLK 128          // persistent blocks (1 per SM)
#define RTH  256          // recurrence threads (8 warps)
#define CHK  64           // K elements per chunk
#define NCH  (HH / CHK)   // 16 chunks per step
#define CHKB 32768        // bytes per packed chunk (hi 16KB + lo 16KB)

// SMEM layout (dynamic, bytes)
#define SM_WHI   0                       // 24 x 1032 bf16 = 49536
#define SM_WLO   49536                   // 49536
#define SM_A     99328                   // 1024-aligned; 2 stages x 32768
#define SM_BIAS  164864                  // 24 floats
#define SM_GATE  164960                  // 8 floats
#define SM_MBAR  164992                  // 2 mbarriers (u64)
#define SM_TOTAL 165120

typedef unsigned long long ull;

// ---------------- device scratch (static; no cudaMalloc) ------------------------
__device__ float g_xproj[(size_t)BB * TT * H3];        // [t][b][3H]
// hidden state, chunk-packed + pre-swizzled: [sel][chunk][hi/lo][row][64] bf16
__device__ __align__(1024) __nv_bfloat16 g_hpk[2][NCH][2][BB][CHK];
__device__ float g_kh[HH];
__device__ float g_khp[H3];
__device__ float g_kxp[KEYLEN * H3];
__device__ float g_gate[HH];
__device__ volatile unsigned g_flags[NBLK];

__device__ __forceinline__ float sigm(float v) { return 1.f / (1.f + __expf(-v)); }

__device__ __forceinline__ void ffma2(ull& d, ull a, ull b) {
    asm("fma.rn.f32x2 %0, %1, %2, %0;" : "+l"(d) : "l"(a), "l"(b));
}
__device__ __forceinline__ float hsum2(ull v) {
    return __int_as_float((unsigned)(v & 0xffffffffull)) + __int_as_float((unsigned)(v >> 32));
}
__device__ __forceinline__ uint32_t smem_to_u32(const void* p) {
    uint32_t a;
    asm("{ .reg .u64 t; cvta.to.shared.u64 t, %1; cvt.u32.u64 %0, t; }" : "=r"(a) : "l"(p));
    return a;
}

#define LDSM_X4(r0, r1, r2, r3, addr) \
    asm volatile("ldmatrix.sync.aligned.m8n8.x4.shared.b16 {%0,%1,%2,%3}, [%4];" \
                 : "=r"(r0), "=r"(r1), "=r"(r2), "=r"(r3) : "r"(addr))

#define MMA16816(c, a, b0, b1) \
    asm volatile("mma.sync.aligned.m16n8k16.row.col.f32.bf16.bf16.f32 " \
                 "{%0,%1,%2,%3},{%4,%5,%6,%7},{%8,%9},{%0,%1,%2,%3};" \
                 : "+f"((c)[0]), "+f"((c)[1]), "+f"((c)[2]), "+f"((c)[3]) \
                 : "r"((a)[0]), "r"((a)[1]), "r"((a)[2]), "r"((a)[3]), "r"(b0), "r"(b1))

#define MBARRIER_INIT(mb, c) \
    asm volatile("mbarrier.init.shared.b64 [%0], %1;" :: "r"((uint32_t)(mb)), "r"((uint32_t)(c)) : "memory")
#define MBAR_ARRIVE_EXPECT(mb, bytes) \
    asm volatile("mbarrier.arrive.expect_tx.shared.b64 _, [%0], %1;" \
                 :: "r"((uint32_t)(mb)), "r"((uint32_t)(bytes)) : "memory")
#define BULK_G2S(dst, src, bytes, mb) \
    asm volatile("cp.async.bulk.shared::cta.global.mbarrier::complete_tx::bytes [%0], [%1], %2, [%3];" \
                 :: "r"((uint32_t)(dst)), "l"(src), "r"((uint32_t)(bytes)), "r"((uint32_t)(mb)) : "memory")
#define MBARRIER_WAIT_PARITY(mb, ph) do { \
    uint32_t _m = (uint32_t)(mb); uint32_t _p = (uint32_t)(ph); uint32_t _d; \
    asm volatile("{\n\t.reg .pred p;\n\t" \
        "mbarrier.try_wait.parity.acquire.cta.shared::cta.b64 p, [%1], %2;\n\t" \
        "selp.b32 %0, 1, 0, p;\n\t}" : "=r"(_d) : "r"(_m), "r"(_p) : "memory"); \
    if (!_d) { \
        asm volatile("{\n\t.reg .pred P1;\n\t" \
            "WL_%=:\n\t" \
            "mbarrier.try_wait.parity.acquire.cta.shared::cta.b64 P1, [%0], %1, 0x989680;\n\t" \
            "@P1 bra.uni WD_%=;\n\tbra.uni WL_%=;\n\tWD_%=:\n\t}" \
            :: "r"(_m), "r"(_p) : "memory"); \
    } } while (0)

// ---------------- init ----------------------------------------------------------
__global__ void zero_kernel() {
    int i = blockIdx.x * blockDim.x + threadIdx.x;
    if (i < (NCH * 2 * BB * CHK) / 2) ((uint32_t*)g_hpk)[i] = 0u;  // zero sel 0
    if (i < HH) g_kh[i] = 0.f;
    if (i < NBLK) g_flags[i] = 0u;
}

// ---------------- xproj (f32x2 scalar GEMM, unchanged) --------------------------
#define XBM 128
#define XBN 64
#define XBK 20
__global__ void xproj_kernel(const int* __restrict__ x, const float* __restrict__ emb,
                             const float* __restrict__ Wih, const float* __restrict__ bih) {
    __shared__ float As[XBM * XBK];
    __shared__ float Bs[XBN * XBK];
    __shared__ int rid[XBM];

    int tid = threadIdx.x;
    int i0 = blockIdx.y * XBM;
    int g0 = blockIdx.x * XBN;

    if (tid < XBM) {
        int i = i0 + tid;
        int t = i / BB, b = i % BB;
        rid[tid] = x[b * TT + t];
    }
    __syncthreads();

    int tx = tid & 15;
    int ty = tid >> 4;

    ull acc[8][4];
#pragma unroll
    for (int r = 0; r < 8; ++r)
#pragma unroll
        for (int c = 0; c < 4; ++c) acc[r][c] = 0ull;

    for (int k0 = 0; k0 < EE; k0 += XBK) {
        for (int idx = tid; idx < XBM * XBK; idx += 256) {
            int row = idx / XBK, kk = idx % XBK;
            As[row * XBK + kk] = emb[(size_t)rid[row] * EE + k0 + kk];
        }
        for (int idx = tid; idx < XBN * XBK; idx += 256) {
            int c = idx / XBK, kk = idx % XBK;
            Bs[c * XBK + kk] = Wih[(size_t)(g0 + c) * EE + k0 + kk];
        }
        __syncthreads();
#pragma unroll
        for (int kp = 0; kp < XBK / 2; ++kp) {
            ull bv[4];
#pragma unroll
            for (int c = 0; c < 4; ++c)
                bv[c] = *(const ull*)(Bs + (tx * 4 + c) * XBK + 2 * kp);
#pragma unroll
            for (int r = 0; r < 8; ++r) {
                ull av = *(const ull*)(As + (ty * 8 + r) * XBK + 2 * kp);
#pragma unroll
                for (int c = 0; c < 4; ++c) ffma2(acc[r][c], av, bv[c]);
            }
        }
        __syncthreads();
    }
#pragma unroll
    for (int r = 0; r < 8; ++r) {
        size_t i = (size_t)(i0 + ty * 8 + r);
#pragma unroll
        for (int c = 0; c < 4; ++c) {
            int g = g0 + tx * 4 + c;
            g_xproj[i * H3 + g] = hsum2(acc[r][c]) + bih[g];
        }
    }
}

// ---------------- key GRU phase (unchanged) -------------------------------------
__global__ void key_xproj_kernel(const int* __restrict__ key_ids, const float* __restrict__ emb,
                                 const float* __restrict__ Wih, const float* __restrict__ bih) {
    __shared__ float ke[KEYLEN][EE];
    int tid = threadIdx.x;
    for (int idx = tid; idx < KEYLEN * EE; idx += 256) {
        int t = idx / EE, k = idx % EE;
        ke[t][k] = emb[(size_t)key_ids[t] * EE + k];
    }
    __syncthreads();
    int g = blockIdx.x * 256 + tid;
    float acc[KEYLEN];
#pragma unroll
    for (int t = 0; t < KEYLEN; ++t) acc[t] = 0.f;
    const float* w = Wih + (size_t)g * EE;
    for (int k = 0; k < EE; ++k) {
        float wv = w[k];
#pragma unroll
        for (int t = 0; t < KEYLEN; ++t) acc[t] += ke[t][k] * wv;
    }
    float bv = bih[g];
#pragma unroll
    for (int t = 0; t < KEYLEN; ++t) g_kxp[t * H3 + g] = acc[t] + bv;
}

__global__ void khp_kernel(const float* __restrict__ Whh, const float* __restrict__ bhh) {
    __shared__ float sh[HH];
    int tid = threadIdx.x;
    for (int i = tid; i < HH; i += 256) sh[i] = g_kh[i];
    __syncthreads();
    int g = blockIdx.x * 256 + tid;
    const float4* w = reinterpret_cast<const float4*>(Whh + (size_t)g * HH);
    float acc = 0.f;
#pragma unroll 4
    for (int k4 = 0; k4 < HH / 4; ++k4) {
        float4 wv = w[k4];
        acc += wv.x * sh[4 * k4] + wv.y * sh[4 * k4 + 1] + wv.z * sh[4 * k4 + 2] + wv.w * sh[4 * k4 + 3];
    }
    g_khp[g] = acc + bhh[g];
}

__global__ void kupdate_kernel(int t) {
    int j = blockIdx.x * 256 + threadIdx.x;
    const float* xp = g_kxp + (size_t)t * H3;
    float r = sigm(xp[j] + g_khp[j]);
    float z = sigm(xp[HH + j] + g_khp[HH + j]);
    float n = tanhf(xp[2 * HH + j] + r * g_khp[2 * HH + j]);
    g_kh[j] = (1.f - z) * n + z * g_kh[j];
}

__global__ void gate_kernel(const float* __restrict__ Wg, const float* __restrict__ bg) {
    __shared__ float sh[HH];
    int tid = threadIdx.x;
    for (int i = tid; i < HH; i += 256) sh[i] = g_kh[i];
    __syncthreads();
    int j = blockIdx.x * 256 + tid;
    const float4* w = reinterpret_cast<const float4*>(Wg + (size_t)j * HH);
    float acc = 0.f;
#pragma unroll 4
    for (int k4 = 0; k4 < HH / 4; ++k4) {
        float4 wv = w[k4];
        acc += wv.x * sh[4 * k4] + wv.y * sh[4 * k4 + 1] + wv.z * sh[4 * k4 + 2] + wv.w * sh[4 * k4 + 3];
    }
    g_gate[j] = sigm(acc + bg[j]);
}

// ---------------- grid barrier ---------------------------------------------------
__device__ __forceinline__ void grid_barrier(unsigned target) {
    __syncthreads();
    if (threadIdx.x == 0) {
        __threadfence();
        g_flags[blockIdx.x] = target;
    }
    if (threadIdx.x < NBLK) {
        while (g_flags[threadIdx.x] < target) { }
    }
    __syncthreads();
}

// ---------------- persistent HMMA recurrence (bulk-copy staging) -----------------
// 128 blocks x 256 threads. W_hh slice (24 rows bf16 hi/lo) in SMEM once. Hidden
// state lives in GMEM chunk-packed + pre-swizzled; per step 16 x 32KB cp.async.bulk
// (double-buffered, mbarrier) stage it; each warp owns an m16 row-tile and runs
// mma.sync m16n8k16 bf16 x 3 passes (hh*wh + hh*wl + hl*wh).
__global__ void __launch_bounds__(RTH, 1)
recur_kernel(const float* __restrict__ Whh, const float* __restrict__ bhh,
             float* __restrict__ out) {
    extern __shared__ char smem[];
    uint32_t smem_base = smem_to_u32(smem);
    float* bias_s = (float*)(smem + SM_BIAS);
    float* gate_s = (float*)(smem + SM_GATE);
    __nv_bfloat16* whi_s = (__nv_bfloat16*)(smem + SM_WHI);
    __nv_bfloat16* wlo_s = (__nv_bfloat16*)(smem + SM_WLO);
    uint32_t mb0 = smem_base + SM_MBAR;
    uint32_t mb1 = smem_base + SM_MBAR + 8;

    int tid = threadIdx.x;
    int lane = tid & 31;
    int w = tid >> 5;
    int j0 = blockIdx.x * 8;

    if (tid == 0) {
        MBARRIER_INIT(mb0, 1);
        MBARRIER_INIT(mb1, 1);
    }
    asm volatile("fence.proxy.async.shared::cta;" ::: "memory");

    // Build W_hh hi/lo slice: rows n = gate*8 + cj, k-contiguous, row stride 1032.
    for (int idx = tid; idx < 24 * HH; idx += RTH) {
        int n = idx >> 10, k = idx & (HH - 1);
        float f = Whh[(size_t)((n >> 3) * HH + j0 + (n & 7)) * HH + k];
        __nv_bfloat16 hi = __float2bfloat16_rn(f);
        __nv_bfloat16 lo = __float2bfloat16_rn(f - __bfloat162float(hi));
        whi_s[n * 1032 + k] = hi;
        wlo_s[n * 1032 + k] = lo;
    }
    if (tid < 24) bias_s[tid] = bhh[(tid >> 3) * HH + j0 + (tid & 7)];
    if (tid < 8)  gate_s[tid] = g_gate[j0 + tid];
    __syncthreads();

    // fragment geometry
    int arow = 16 * w + (lane & 15);        // A row for ldmatrix
    int ar7 = arow & 7;
    uint32_t arowb = (uint32_t)(arow * 128);
    int lhalf = lane >> 4;
    uint32_t b_off[3];
#pragma unroll
    for (int nt = 0; nt < 3; ++nt)
        b_off[nt] = (uint32_t)((nt * 8 + (lane & 7)) * 2064 + (lane >> 3) * 16);

    int row0 = 16 * w + (lane >> 2);        // epilogue rows row0, row0+8
    int jc = 2 * (lane & 3);                // col pair within 8
    float gv = gate_s[jc], gv1 = gate_s[jc + 1];
    float b_r0 = bias_s[jc],      b_r1 = bias_s[jc + 1];
    float b_z0 = bias_s[8 + jc],  b_z1 = bias_s[8 + jc + 1];
    float b_n0 = bias_s[16 + jc], b_n1 = bias_s[16 + jc + 1];

    // packed-h addressing for this block's columns (chunk constant per block)
    int mychunk = j0 >> 6;
    int cw = (j0 & 63) + jc;                // within-chunk col
    uint32_t ep0 = (uint32_t)(((row0 * 128 + cw * 2) ^ ((row0 & 7) << 4)));
    uint32_t ep1 = (uint32_t)((((row0 + 8) * 128 + cw * 2) ^ (((row0 + 8) & 7) << 4)));

    uint32_t ph0 = 0, ph1 = 0;

#pragma unroll 1
    for (int t = 0; t < TT; ++t) {
        int sel = t & 1;
        const char* hsrc = (const char*)&g_hpk[sel][0][0][0][0];
        char* hdst = (char*)&g_hpk[sel ^ 1][0][0][0][0];
        const float* xp = g_xproj + (size_t)t * BB * H3;

        // issue chunks 0 and 1 immediately
        if (tid == 0) {
            MBAR_ARRIVE_EXPECT(mb0, CHKB);
            BULK_G2S(smem_base + SM_A, hsrc, CHKB, mb0);
            MBAR_ARRIVE_EXPECT(mb1, CHKB);
            BULK_G2S(smem_base + SM_A + CHKB, hsrc + CHKB, CHKB, mb1);
        }

        // prefetch epilogue inputs (long-latency, independent of MMA)
        const float* xpr0 = xp + (size_t)row0 * H3 + j0 + jc;
        const float* xpr1 = xp + (size_t)(row0 + 8) * H3 + j0 + jc;
        float2 xr0 = __ldcs((const float2*)(xpr0));
        float2 xz0 = __ldcs((const float2*)(xpr0 + HH));
        float2 xn0 = __ldcs((const float2*)(xpr0 + 2 * HH));
        float2 xr1 = __ldcs((const float2*)(xpr1));
        float2 xz1 = __ldcs((const float2*)(xpr1 + HH));
        float2 xn1 = __ldcs((const float2*)(xpr1 + 2 * HH));
        const char* hcs = hsrc + (size_t)mychunk * CHKB;
        __nv_bfloat162 hh0 = *(const __nv_bfloat162*)(hcs + ep0);
        __nv_bfloat162 hl0 = *(const __nv_bfloat162*)(hcs + 16384 + ep0);
        __nv_bfloat162 hh1 = *(const __nv_bfloat162*)(hcs + ep1);
        __nv_bfloat162 hl1 = *(const __nv_bfloat162*)(hcs + 16384 + ep1);
        float hold00 = __low2float(hh0) + __low2float(hl0);
        float hold01 = __high2float(hh0) + __high2float(hl0);
        float hold10 = __low2float(hh1) + __low2float(hl1);
        float hold11 = __high2float(hh1) + __high2float(hl1);

        float cacc[3][4];
#pragma unroll
        for (int nt = 0; nt < 3; ++nt)
#pragma unroll
            for (int i = 0; i < 4; ++i) cacc[nt][i] = 0.f;

#pragma unroll 1
        for (int c = 0; c < NCH; ++c) {
            int st = c & 1;
            if (st == 0) { MBARRIER_WAIT_PARITY(mb0, ph0); ph0 ^= 1; }
            else         { MBARRIER_WAIT_PARITY(mb1, ph1); ph1 ^= 1; }

            uint32_t sbase = smem_base + SM_A + (uint32_t)(st * CHKB) + arowb;
#pragma unroll
            for (int s2 = 0; s2 < 2; ++s2) {
                uint32_t bh[3][4], bl[3][4];
#pragma unroll
                for (int nt = 0; nt < 3; ++nt) {
                    uint32_t bb = smem_base + b_off[nt] + (uint32_t)(c * 128 + s2 * 64);
                    LDSM_X4(bh[nt][0], bh[nt][1], bh[nt][2], bh[nt][3], bb + SM_WHI);
                    LDSM_X4(bl[nt][0], bl[nt][1], bl[nt][2], bl[nt][3], bb + SM_WLO);
                }
#pragma unroll
                for (int s = 0; s < 2; ++s) {
                    int u = s2 * 4 + s * 2 + lhalf;
                    uint32_t aa = sbase + (uint32_t)(((u ^ ar7)) << 4);
                    uint32_t ah[4], al[4];
                    LDSM_X4(ah[0], ah[1], ah[2], ah[3], aa);
                    LDSM_X4(al[0], al[1], al[2], al[3], aa + 16384);
#pragma unroll
                    for (int nt = 0; nt < 3; ++nt) {
                        MMA16816(cacc[nt], ah, bh[nt][2 * s], bh[nt][2 * s + 1]);
                        MMA16816(cacc[nt], ah, bl[nt][2 * s], bl[nt][2 * s + 1]);
                        MMA16816(cacc[nt], al, bh[nt][2 * s], bh[nt][2 * s + 1]);
                    }
                }
            }
            __syncthreads();   // all warps done reading stage st

            if (c + 2 < NCH && tid == 0) {
                uint32_t mb = st == 0 ? mb0 : mb1;
                MBAR_ARRIVE_EXPECT(mb, CHKB);
                BULK_G2S(smem_base + SM_A + (uint32_t)(st * CHKB),
                         hsrc + (size_t)(c + 2) * CHKB, CHKB, mb);
            }
        }

        // epilogue: GRU gates + key gate; write packed hi/lo (or fp32 out last step)
        char* hcd = hdst + (size_t)mychunk * CHKB;
#pragma unroll
        for (int half = 0; half < 2; ++half) {
            int row = row0 + half * 8;
            int ib = 2 * half;
            float xr_ = half ? xr1.x : xr0.x, xr_1 = half ? xr1.y : xr0.y;
            float xz_ = half ? xz1.x : xz0.x, xz_1 = half ? xz1.y : xz0.y;
            float xn_ = half ? xn1.x : xn0.x, xn_1 = half ? xn1.y : xn0.y;
            float ho0 = half ? hold10 : hold00;
            float ho1 = half ? hold11 : hold01;

            float rg0 = sigm(xr_ + cacc[0][ib] + b_r0);
            float zg0 = sigm(xz_ + cacc[1][ib] + b_z0);
            float ng0 = tanhf(xn_ + rg0 * (cacc[2][ib] + b_n0));
            float o0 = gv * ((1.f - zg0) * ng0 + zg0 * ho0);

            float rg1 = sigm(xr_1 + cacc[0][ib + 1] + b_r1);
            float zg1 = sigm(xz_1 + cacc[1][ib + 1] + b_z1);
            float ng1 = tanhf(xn_1 + rg1 * (cacc[2][ib + 1] + b_n1));
            float o1 = gv1 * ((1.f - zg1) * ng1 + zg1 * ho1);

            if (t == TT - 1) {
                *(float2*)(out + (size_t)row * HH + j0 + jc) = make_float2(o0, o1);
            } else {
                __nv_bfloat16 h0 = __float2bfloat16_rn(o0);
                __nv_bfloat16 h1 = __float2bfloat16_rn(o1);
                __nv_bfloat162 hv; hv.x = h0; hv.y = h1;
                __nv_bfloat162 lv;
                lv.x = __float2bfloat16_rn(o0 - __bfloat162float(h0));
                lv.y = __float2bfloat16_rn(o1 - __bfloat162float(h1));
                uint32_t ep = half ? ep1 : ep0;
                *(__nv_bfloat162*)(hcd + ep) = hv;
                *(__nv_bfloat162*)(hcd + 16384 + ep) = lv;
            }
        }

        if (t < TT - 1) grid_barrier((unsigned)(t + 1));
    }
}

// ---------------- launch ---------------------------------------------------------
extern "C" void kernel_launch(void* const* d_in, const int* in_sizes, int n_in,
                              void* d_out, int out_size) {
    const int* x        = (const int*)d_in[0];
    const int* key_ids  = (const int*)d_in[1];
    const float* emb    = (const float*)d_in[2];
    const float* W_ih   = (const float*)d_in[3];
    const float* W_hh   = (const float*)d_in[4];
    const float* b_ih   = (const float*)d_in[5];
    const float* b_hh   = (const float*)d_in[6];
    const float* W_g    = (const float*)d_in[7];
    const float* b_g    = (const float*)d_in[8];
    float* out = (float*)d_out;

    cudaFuncSetAttribute(recur_kernel, cudaFuncAttributeMaxDynamicSharedMemorySize, SM_TOTAL);

    zero_kernel<<<(BB * HH + 255) / 256, 256>>>();

    // key GRU phase (tiny)
    key_xproj_kernel<<<H3 / 256, 256>>>(key_ids, emb, W_ih, b_ih);
    for (int t = 0; t < KEYLEN; ++t) {
        khp_kernel<<<H3 / 256, 256>>>(W_hh, b_hh);
        kupdate_kernel<<<HH / 256, 256>>>(t);
    }
    gate_kernel<<<HH / 256, 256>>>(W_g, b_g);

    // input projection for the main sequence
    dim3 xg(H3 / XBN, (BB * TT) / XBM);
    xproj_kernel<<<xg, 256>>>(x, emb, W_ih, b_ih);

    // persistent HMMA recurrence: all 512 steps in one kernel
    recur_kernel<<<NBLK, RTH, SM_TOTAL>>>(W_hh, b_hh, out);
}

// round 12
// speedup vs baseline: 4.0566x; 1.0151x over previous
#include <cuda_runtime.h>
#include <cuda_bf16.h>
#include <math.h>
#include <stdint.h>

#define BB 128
#define TT 512
#define EE 300
#define HH 1024
#define H3 3072
#define KEYLEN 15

#define NBLK 128          // persistent blocks (1 per SM)
#define RTH  256          // recurrence threads (8 warps)
#define CHK  64           // K elements per chunk
#define NCH  (HH / CHK)   // 16 chunks per step
#define CHKB 32768        // bytes per packed chunk (hi 16KB + lo 16KB)
#define NSTG 3            // pipeline stages

// recur SMEM layout (dynamic, bytes)
#define SM_WHI   0                       // 24 x 1032 bf16 = 49536
#define SM_WLO   49536                   // 49536
#define SM_A     99328                   // 1024-aligned; 3 stages x 32768
#define SM_BIAS  197632                  // 24 floats
#define SM_GATE  197728                  // 8 floats
#define SM_MBAR  197760                  // 3 mbarriers (u64)
#define SM_TOTAL 197888

// keyall SMEM layout (dynamic, bytes)
#define KA_KE    0                       // 15*300 floats = 18000
#define KA_WSL   18048                   // 24*1024 floats = 98304
#define KA_KXP   116352                  // 15*24 floats = 1440
#define KA_KH    117792                  // 1024 floats = 4096
#define KA_HP    121888                  // 24 floats = 96
#define KA_TOTAL 122112

typedef unsigned long long ull;

// ---------------- device scratch (static; no cudaMalloc) ------------------------
__device__ float g_xproj[(size_t)BB * TT * H3];        // [t][b][3H]
// hidden state, chunk-packed + pre-swizzled: [sel][chunk][hi/lo][row][64] bf16
__device__ __align__(1024) __nv_bfloat16 g_hpk[2][NCH][2][BB][CHK];
__device__ float g_kh[HH];
__device__ float g_gate[HH];
__device__ volatile unsigned g_flags[NBLK];
__device__ volatile unsigned g_kflags[NBLK];

__device__ __forceinline__ float sigm(float v) {
    return __fdividef(1.f, 1.f + __expf(-v));
}
__device__ __forceinline__ float tanh_fast(float x) {
    // 1 - 2/(e^{2x}+1); exact limits at +-inf, ~1e-6 relative error
    float e = __expf(2.f * x);
    return 1.f - __fdividef(2.f, e + 1.f);
}

__device__ __forceinline__ void ffma2(ull& d, ull a, ull b) {
    asm("fma.rn.f32x2 %0, %1, %2, %0;" : "+l"(d) : "l"(a), "l"(b));
}
__device__ __forceinline__ float hsum2(ull v) {
    return __int_as_float((unsigned)(v & 0xffffffffull)) + __int_as_float((unsigned)(v >> 32));
}
__device__ __forceinline__ uint32_t smem_to_u32(const void* p) {
    uint32_t a;
    asm("{ .reg .u64 t; cvta.to.shared.u64 t, %1; cvt.u32.u64 %0, t; }" : "=r"(a) : "l"(p));
    return a;
}

#define LDSM_X4(r0, r1, r2, r3, addr) \
    asm volatile("ldmatrix.sync.aligned.m8n8.x4.shared.b16 {%0,%1,%2,%3}, [%4];" \
                 : "=r"(r0), "=r"(r1), "=r"(r2), "=r"(r3) : "r"(addr))

#define MMA16816(c, a, b0, b1) \
    asm volatile("mma.sync.aligned.m16n8k16.row.col.f32.bf16.bf16.f32 " \
                 "{%0,%1,%2,%3},{%4,%5,%6,%7},{%8,%9},{%0,%1,%2,%3};" \
                 : "+f"((c)[0]), "+f"((c)[1]), "+f"((c)[2]), "+f"((c)[3]) \
                 : "r"((a)[0]), "r"((a)[1]), "r"((a)[2]), "r"((a)[3]), "r"(b0), "r"(b1))

#define MBARRIER_INIT(mb, c) \
    asm volatile("mbarrier.init.shared.b64 [%0], %1;" :: "r"((uint32_t)(mb)), "r"((uint32_t)(c)) : "memory")
#define MBAR_ARRIVE_EXPECT(mb, bytes) \
    asm volatile("mbarrier.arrive.expect_tx.shared.b64 _, [%0], %1;" \
                 :: "r"((uint32_t)(mb)), "r"((uint32_t)(bytes)) : "memory")
#define BULK_G2S(dst, src, bytes, mb) \
    asm volatile("cp.async.bulk.shared::cta.global.mbarrier::complete_tx::bytes [%0], [%1], %2, [%3];" \
                 :: "r"((uint32_t)(dst)), "l"(src), "r"((uint32_t)(bytes)), "r"((uint32_t)(mb)) : "memory")
#define MBARRIER_WAIT_PARITY(mb, ph) do { \
    uint32_t _m = (uint32_t)(mb); uint32_t _p = (uint32_t)(ph); uint32_t _d; \
    asm volatile("{\n\t.reg .pred p;\n\t" \
        "mbarrier.try_wait.parity.acquire.cta.shared::cta.b64 p, [%1], %2;\n\t" \
        "selp.b32 %0, 1, 0, p;\n\t}" : "=r"(_d) : "r"(_m), "r"(_p) : "memory"); \
    if (!_d) { \
        asm volatile("{\n\t.reg .pred P1;\n\t" \
            "WL_%=:\n\t" \
            "mbarrier.try_wait.parity.acquire.cta.shared::cta.b64 P1, [%0], %1, 0x989680;\n\t" \
            "@P1 bra.uni WD_%=;\n\tbra.uni WL_%=;\n\tWD_%=:\n\t}" \
            :: "r"(_m), "r"(_p) : "memory"); \
    } } while (0)

// ---------------- init ----------------------------------------------------------
__global__ void zero_kernel() {
    int i = blockIdx.x * blockDim.x + threadIdx.x;
    if (i < (NCH * 2 * BB * CHK) / 2) ((uint32_t*)g_hpk)[i] = 0u;  // zero sel 0
    if (i < HH) g_kh[i] = 0.f;
    if (i < NBLK) { g_flags[i] = 0u; g_kflags[i] = 0u; }
}

// ---------------- pad kernels (ncu launch-index alignment) -----------------------
__global__ void pad_kernel() {}

// ---------------- xproj (f32x2 scalar GEMM) --------------------------------------
#define XBM 128
#define XBN 64
#define XBK 20
__global__ void xproj_kernel(const int* __restrict__ x, const float* __restrict__ emb,
                             const float* __restrict__ Wih, const float* __restrict__ bih) {
    __shared__ float As[XBM * XBK];
    __shared__ float Bs[XBN * XBK];
    __shared__ int rid[XBM];

    int tid = threadIdx.x;
    int i0 = blockIdx.y * XBM;
    int g0 = blockIdx.x * XBN;

    if (tid < XBM) {
        int i = i0 + tid;
        int t = i / BB, b = i % BB;
        rid[tid] = x[b * TT + t];
    }
    __syncthreads();

    int tx = tid & 15;
    int ty = tid >> 4;

    ull acc[8][4];
#pragma unroll
    for (int r = 0; r < 8; ++r)
#pragma unroll
        for (int c = 0; c < 4; ++c) acc[r][c] = 0ull;

    for (int k0 = 0; k0 < EE; k0 += XBK) {
        for (int idx = tid; idx < XBM * XBK; idx += 256) {
            int row = idx / XBK, kk = idx % XBK;
            As[row * XBK + kk] = emb[(size_t)rid[row] * EE + k0 + kk];
        }
        for (int idx = tid; idx < XBN * XBK; idx += 256) {
            int c = idx / XBK, kk = idx % XBK;
            Bs[c * XBK + kk] = Wih[(size_t)(g0 + c) * EE + k0 + kk];
        }
        __syncthreads();
#pragma unroll
        for (int kp = 0; kp < XBK / 2; ++kp) {
            ull bv[4];
#pragma unroll
            for (int c = 0; c < 4; ++c)
                bv[c] = *(const ull*)(Bs + (tx * 4 + c) * XBK + 2 * kp);
#pragma unroll
            for (int r = 0; r < 8; ++r) {
                ull av = *(const ull*)(As + (ty * 8 + r) * XBK + 2 * kp);
#pragma unroll
                for (int c = 0; c < 4; ++c) ffma2(acc[r][c], av, bv[c]);
            }
        }
        __syncthreads();
    }
#pragma unroll
    for (int r = 0; r < 8; ++r) {
        size_t i = (size_t)(i0 + ty * 8 + r);
#pragma unroll
        for (int c = 0; c < 4; ++c) {
            int g = g0 + tx * 4 + c;
            g_xproj[i * H3 + g] = hsum2(acc[r][c]) + bih[g];
        }
    }
}

// ---------------- barriers -------------------------------------------------------
__device__ __forceinline__ void grid_barrier(unsigned target) {
    __syncthreads();
    if (threadIdx.x == 0) {
        __threadfence();
        g_flags[blockIdx.x] = target;
    }
    if (threadIdx.x < NBLK) {
        while (g_flags[threadIdx.x] < target) { }
    }
    __syncthreads();
}
__device__ __forceinline__ void kgrid_barrier(unsigned target) {
    __syncthreads();
    if (threadIdx.x == 0) {
        __threadfence();
        g_kflags[blockIdx.x] = target;
    }
    if (threadIdx.x < NBLK) {
        while (g_kflags[threadIdx.x] < target) { }
    }
    __syncthreads();
}

// ---------------- fused key-GRU kernel -------------------------------------------
// 128 persistent blocks x 256 threads. Block owns 8 hidden cols (24 gate rows).
// Entire 15-step key GRU + gate projection in one kernel; W_hh slice in SMEM.
__global__ void __launch_bounds__(256, 1)
keyall_kernel(const int* __restrict__ key_ids, const float* __restrict__ emb,
              const float* __restrict__ Wih, const float* __restrict__ Whh,
              const float* __restrict__ bih, const float* __restrict__ bhh,
              const float* __restrict__ Wg, const float* __restrict__ bg) {
    extern __shared__ char smem[];
    float* ke    = (float*)(smem + KA_KE);
    float* Wsl   = (float*)(smem + KA_WSL);
    float* kxp_s = (float*)(smem + KA_KXP);
    float* kh_s  = (float*)(smem + KA_KH);
    float* hp_s  = (float*)(smem + KA_HP);

    int tid = threadIdx.x;
    int lane = tid & 31, w = tid >> 5;
    int j0 = blockIdx.x * 8;

    for (int i = tid; i < KEYLEN * EE; i += 256) {
        int t = i / EE, e = i % EE;
        ke[i] = emb[(size_t)key_ids[t] * EE + e];
    }
    for (int i = tid; i < 24 * HH; i += 256) {
        int n = i >> 10, k = i & 1023;
        Wsl[i] = Whh[(size_t)((n >> 3) * HH + j0 + (n & 7)) * HH + k];
    }
    __syncthreads();

    // key input projection: kxp[t][n]
    for (int i = tid; i < KEYLEN * 24; i += 256) {
        int t = i / 24, n = i % 24;
        int grow = (n >> 3) * HH + j0 + (n & 7);
        const float* wr = Wih + (size_t)grow * EE;
        float acc = 0.f;
        for (int e = 0; e < EE; ++e) acc += wr[e] * ke[t * EE + e];
        kxp_s[i] = acc + bih[grow];
    }
    __syncthreads();

    // 15 recurrent steps with grid barrier
    for (int t = 0; t < KEYLEN; ++t) {
        for (int i = tid; i < HH; i += 256) kh_s[i] = __ldcg(&g_kh[i]);
        __syncthreads();
#pragma unroll
        for (int rr = 0; rr < 3; ++rr) {
            int n = w * 3 + rr;
            const float* wr = Wsl + n * HH;
            float a = 0.f;
            for (int k = lane; k < HH; k += 32) a += wr[k] * kh_s[k];
#pragma unroll
            for (int o = 16; o; o >>= 1) a += __shfl_xor_sync(0xffffffffu, a, o);
            if (lane == 0) hp_s[n] = a;
        }
        __syncthreads();
        if (tid < 8) {
            int j = j0 + tid;
            float r = sigm(kxp_s[t * 24 + tid] + hp_s[tid] + bhh[j]);
            float z = sigm(kxp_s[t * 24 + 8 + tid] + hp_s[8 + tid] + bhh[HH + j]);
            float n2 = tanh_fast(kxp_s[t * 24 + 16 + tid] + r * (hp_s[16 + tid] + bhh[2 * HH + j]));
            g_kh[j] = (1.f - z) * n2 + z * kh_s[j];
        }
        kgrid_barrier((unsigned)(t + 1));
    }

    // gate = sigmoid(W_g @ kh + b_g), one col per warp
    for (int i = tid; i < HH; i += 256) kh_s[i] = __ldcg(&g_kh[i]);
    __syncthreads();
    {
        int j = j0 + w;
        const float* wr = Wg + (size_t)j * HH;
        float a = 0.f;
        for (int k = lane; k < HH; k += 32) a += wr[k] * kh_s[k];
#pragma unroll
        for (int o = 16; o; o >>= 1) a += __shfl_xor_sync(0xffffffffu, a, o);
        if (lane == 0) g_gate[j] = sigm(a + bg[j]);
    }
}

// ---------------- persistent HMMA recurrence (3-stage bulk pipeline) -------------
__global__ void __launch_bounds__(RTH, 1)
recur_kernel(const float* __restrict__ Whh, const float* __restrict__ bhh,
             float* __restrict__ out) {
    extern __shared__ char smem[];
    uint32_t smem_base = smem_to_u32(smem);
    float* bias_s = (float*)(smem + SM_BIAS);
    float* gate_s = (float*)(smem + SM_GATE);
    __nv_bfloat16* whi_s = (__nv_bfloat16*)(smem + SM_WHI);
    __nv_bfloat16* wlo_s = (__nv_bfloat16*)(smem + SM_WLO);

    int tid = threadIdx.x;
    int lane = tid & 31;
    int w = tid >> 5;
    int j0 = blockIdx.x * 8;

    if (tid == 0) {
#pragma unroll
        for (int s = 0; s < NSTG; ++s) MBARRIER_INIT(smem_base + SM_MBAR + s * 8, 1);
    }
    asm volatile("fence.proxy.async.shared::cta;" ::: "memory");

    // Build W_hh hi/lo slice: rows n = gate*8 + cj, k-contiguous, row stride 1032.
    for (int idx = tid; idx < 24 * HH; idx += RTH) {
        int n = idx >> 10, k = idx & (HH - 1);
        float f = Whh[(size_t)((n >> 3) * HH + j0 + (n & 7)) * HH + k];
        __nv_bfloat16 hi = __float2bfloat16_rn(f);
        __nv_bfloat16 lo = __float2bfloat16_rn(f - __bfloat162float(hi));
        whi_s[n * 1032 + k] = hi;
        wlo_s[n * 1032 + k] = lo;
    }
    if (tid < 24) bias_s[tid] = bhh[(tid >> 3) * HH + j0 + (tid & 7)];
    if (tid < 8)  gate_s[tid] = g_gate[j0 + tid];
    __syncthreads();

    // fragment geometry
    int arow = 16 * w + (lane & 15);        // A row for ldmatrix
    int ar7 = arow & 7;
    uint32_t arowb = (uint32_t)(arow * 128);
    int lhalf = lane >> 4;
    uint32_t b_off[3];
#pragma unroll
    for (int nt = 0; nt < 3; ++nt)
        b_off[nt] = (uint32_t)((nt * 8 + (lane & 7)) * 2064 + (lane >> 3) * 16);

    int row0 = 16 * w + (lane >> 2);        // epilogue rows row0, row0+8
    int jc = 2 * (lane & 3);                // col pair within 8
    float gv = gate_s[jc], gv1 = gate_s[jc + 1];
    float b_r0 = bias_s[jc],      b_r1 = bias_s[jc + 1];
    float b_z0 = bias_s[8 + jc],  b_z1 = bias_s[8 + jc + 1];
    float b_n0 = bias_s[16 + jc], b_n1 = bias_s[16 + jc + 1];

    // packed-h addressing for this block's columns
    int mychunk = j0 >> 6;
    int cw = (j0 & 63) + jc;
    uint32_t ep0 = (uint32_t)(((row0 * 128 + cw * 2) ^ ((row0 & 7) << 4)));
    uint32_t ep1 = (uint32_t)((((row0 + 8) * 128 + cw * 2) ^ (((row0 + 8) & 7) << 4)));

    unsigned phbits = 0;     // per-stage mbarrier phase
    int stg = 0;             // rotating stage index (persists across steps)

#pragma unroll 1
    for (int t = 0; t < TT; ++t) {
        int sel = t & 1;
        const char* hsrc = (const char*)&g_hpk[sel][0][0][0][0];
        char* hdst = (char*)&g_hpk[sel ^ 1][0][0][0][0];
        const float* xp = g_xproj + (size_t)t * BB * H3;

        // prologue: fill the 3-stage pipeline
        if (tid == 0) {
            int s = stg;
#pragma unroll
            for (int p = 0; p < NSTG; ++p) {
                uint32_t mb = smem_base + SM_MBAR + s * 8;
                MBAR_ARRIVE_EXPECT(mb, CHKB);
                BULK_G2S(smem_base + SM_A + s * CHKB, hsrc + (size_t)p * CHKB, CHKB, mb);
                s = (s + 1 == NSTG) ? 0 : s + 1;
            }
        }

        // prefetch epilogue inputs (long-latency, independent of MMA)
        const float* xpr0 = xp + (size_t)row0 * H3 + j0 + jc;
        const float* xpr1 = xp + (size_t)(row0 + 8) * H3 + j0 + jc;
        float2 xr0 = __ldcs((const float2*)(xpr0));
        float2 xz0 = __ldcs((const float2*)(xpr0 + HH));
        float2 xn0 = __ldcs((const float2*)(xpr0 + 2 * HH));
        float2 xr1 = __ldcs((const float2*)(xpr1));
        float2 xz1 = __ldcs((const float2*)(xpr1 + HH));
        float2 xn1 = __ldcs((const float2*)(xpr1 + 2 * HH));
        const char* hcs = hsrc + (size_t)mychunk * CHKB;
        __nv_bfloat162 hh0 = *(const __nv_bfloat162*)(hcs + ep0);
        __nv_bfloat162 hl0 = *(const __nv_bfloat162*)(hcs + 16384 + ep0);
        __nv_bfloat162 hh1 = *(const __nv_bfloat162*)(hcs + ep1);
        __nv_bfloat162 hl1 = *(const __nv_bfloat162*)(hcs + 16384 + ep1);
        float hold00 = __low2float(hh0) + __low2float(hl0);
        float hold01 = __high2float(hh0) + __high2float(hl0);
        float hold10 = __low2float(hh1) + __low2float(hl1);
        float hold11 = __high2float(hh1) + __high2float(hl1);

        float cacc[3][4];
#pragma unroll
        for (int nt = 0; nt < 3; ++nt)
#pragma unroll
            for (int i = 0; i < 4; ++i) cacc[nt][i] = 0.f;

#pragma unroll 1
        for (int c = 0; c < NCH; ++c) {
            uint32_t mb = smem_base + SM_MBAR + stg * 8;
            MBARRIER_WAIT_PARITY(mb, (phbits >> stg) & 1);
            phbits ^= (1u << stg);

            uint32_t sbase = smem_base + SM_A + (uint32_t)(stg * CHKB) + arowb;
#pragma unroll
            for (int s2 = 0; s2 < 2; ++s2) {
                uint32_t bh[3][4], bl[3][4];
#pragma unroll
                for (int nt = 0; nt < 3; ++nt) {
                    uint32_t bb = smem_base + b_off[nt] + (uint32_t)(c * 128 + s2 * 64);
                    LDSM_X4(bh[nt][0], bh[nt][1], bh[nt][2], bh[nt][3], bb + SM_WHI);
                    LDSM_X4(bl[nt][0], bl[nt][1], bl[nt][2], bl[nt][3], bb + SM_WLO);
                }
#pragma unroll
                for (int s = 0; s < 2; ++s) {
                    int u = s2 * 4 + s * 2 + lhalf;
                    uint32_t aa = sbase + (uint32_t)(((u ^ ar7)) << 4);
                    uint32_t ah[4], al[4];
                    LDSM_X4(ah[0], ah[1], ah[2], ah[3], aa);
                    LDSM_X4(al[0], al[1], al[2], al[3], aa + 16384);
#pragma unroll
                    for (int nt = 0; nt < 3; ++nt) {
                        MMA16816(cacc[nt], ah, bh[nt][2 * s], bh[nt][2 * s + 1]);
                        MMA16816(cacc[nt], ah, bl[nt][2 * s], bl[nt][2 * s + 1]);
                        MMA16816(cacc[nt], al, bh[nt][2 * s], bh[nt][2 * s + 1]);
                    }
                }
            }
            __syncthreads();   // all warps done reading this stage

            if (c + NSTG < NCH && tid == 0) {
                MBAR_ARRIVE_EXPECT(mb, CHKB);
                BULK_G2S(smem_base + SM_A + (uint32_t)(stg * CHKB),
                         hsrc + (size_t)(c + NSTG) * CHKB, CHKB, mb);
            }
            stg = (stg + 1 == NSTG) ? 0 : stg + 1;
        }

        // epilogue: GRU gates + key gate; write packed hi/lo (or fp32 out last step)
        char* hcd = hdst + (size_t)mychunk * CHKB;
#pragma unroll
        for (int half = 0; half < 2; ++half) {
            int row = row0 + half * 8;
            int ib = 2 * half;
            float xr_ = half ? xr1.x : xr0.x, xr_1 = half ? xr1.y : xr0.y;
            float xz_ = half ? xz1.x : xz0.x, xz_1 = half ? xz1.y : xz0.y;
            float xn_ = half ? xn1.x : xn0.x, xn_1 = half ? xn1.y : xn0.y;
            float ho0 = half ? hold10 : hold00;
            float ho1 = half ? hold11 : hold01;

            float rg0 = sigm(xr_ + cacc[0][ib] + b_r0);
            float zg0 = sigm(xz_ + cacc[1][ib] + b_z0);
            float ng0 = tanh_fast(xn_ + rg0 * (cacc[2][ib] + b_n0));
            float o0 = gv * ((1.f - zg0) * ng0 + zg0 * ho0);

            float rg1 = sigm(xr_1 + cacc[0][ib + 1] + b_r1);
            float zg1 = sigm(xz_1 + cacc[1][ib + 1] + b_z1);
            float ng1 = tanh_fast(xn_1 + rg1 * (cacc[2][ib + 1] + b_n1));
            float o1 = gv1 * ((1.f - zg1) * ng1 + zg1 * ho1);

            if (t == TT - 1) {
                *(float2*)(out + (size_t)row * HH + j0 + jc) = make_float2(o0, o1);
            } else {
                __nv_bfloat16 h0 = __float2bfloat16_rn(o0);
                __nv_bfloat16 h1 = __float2bfloat16_rn(o1);
                __nv_bfloat162 hv; hv.x = h0; hv.y = h1;
                __nv_bfloat162 lv;
                lv.x = __float2bfloat16_rn(o0 - __bfloat162float(h0));
                lv.y = __float2bfloat16_rn(o1 - __bfloat162float(h1));
                uint32_t ep = half ? ep1 : ep0;
                *(__nv_bfloat162*)(hcd + ep) = hv;
                *(__nv_bfloat162*)(hcd + 16384 + ep) = lv;
            }
        }

        if (t < TT - 1) grid_barrier((unsigned)(t + 1));
    }
}

// ---------------- launch ---------------------------------------------------------
extern "C" void kernel_launch(void* const* d_in, const int* in_sizes, int n_in,
                              void* d_out, int out_size) {
    const int* x        = (const int*)d_in[0];
    const int* key_ids  = (const int*)d_in[1];
    const float* emb    = (const float*)d_in[2];
    const float* W_ih   = (const float*)d_in[3];
    const float* W_hh   = (const float*)d_in[4];
    const float* b_ih   = (const float*)d_in[5];
    const float* b_hh   = (const float*)d_in[6];
    const float* W_g    = (const float*)d_in[7];
    const float* b_g    = (const float*)d_in[8];
    float* out = (float*)d_out;

    cudaFuncSetAttribute(recur_kernel, cudaFuncAttributeMaxDynamicSharedMemorySize, SM_TOTAL);
    cudaFuncSetAttribute(keyall_kernel, cudaFuncAttributeMaxDynamicSharedMemorySize, KA_TOTAL);

    // launch indices fixed so ncu (-s 5 -c 1) profiles recur_kernel (index 5)
    zero_kernel<<<(BB * HH + 255) / 256, 256>>>();                               // 0
    keyall_kernel<<<NBLK, 256, KA_TOTAL>>>(key_ids, emb, W_ih, W_hh,
                                           b_ih, b_hh, W_g, b_g);                // 1
    dim3 xg(H3 / XBN, (BB * TT) / XBM);
    xproj_kernel<<<xg, 256>>>(x, emb, W_ih, b_ih);                               // 2
    pad_kernel<<<1, 32>>>();                                                     // 3
    pad_kernel<<<1, 32>>>();                                                     // 4
    recur_kernel<<<NBLK, RTH, SM_TOTAL>>>(W_hh, b_hh, out);                      // 5
}

// round 13
// speedup vs baseline: 4.0599x; 1.0008x over previous
#include <cuda_runtime.h>
#include <cuda_bf16.h>
#include <math.h>
#include <stdint.h>

#define BB 128
#define TT 512
#define EE 300
#define HH 1024
#define H3 3072
#define KEYLEN 15

#define NBLK 128          // persistent blocks (1 per SM)
#define RTH  256          // recurrence threads (8 warps)
#define CHK  64           // K elements per chunk
#define NCH  (HH / CHK)   // 16 chunks per step
#define CHKB 32768        // bytes per packed chunk (hi 16KB + lo 16KB)
#define NSTG 3            // pipeline stages

// recur SMEM layout (dynamic, bytes)
#define SM_WHI   0                       // 24 x 1032 bf16 = 49536
#define SM_WLO   49536                   // 49536
#define SM_A     99328                   // 1024-aligned; 3 stages x 32768
#define SM_BIAS  197632                  // 24 floats
#define SM_GATE  197728                  // 8 floats
#define SM_MBAR  197760                  // 3 mbarriers (u64)
#define SM_TOTAL 197888

// keyall SMEM layout (dynamic, bytes)
#define KA_KE    0                       // 15*300 floats = 18000
#define KA_WSL   18048                   // 24*1024 floats = 98304
#define KA_KXP   116352                  // 15*24 floats = 1440
#define KA_KH    117792                  // 1024 floats = 4096
#define KA_HP    121888                  // 24 floats = 96
#define KA_TOTAL 122112

typedef unsigned long long ull;

// ---------------- device scratch (static; no cudaMalloc) ------------------------
__device__ float g_xproj[(size_t)BB * TT * H3];        // [t][b][3H]
// hidden state, chunk-packed + pre-swizzled: [sel][chunk][hi/lo][row][64] bf16
__device__ __align__(1024) __nv_bfloat16 g_hpk[2][NCH][2][BB][CHK];
__device__ float g_kh[HH];
__device__ float g_gate[HH];
__device__ volatile unsigned g_flags[NBLK];
__device__ volatile unsigned g_kflags[NBLK];

__device__ __forceinline__ float sigm(float v) {
    return __fdividef(1.f, 1.f + __expf(-v));
}
__device__ __forceinline__ float tanh_fast(float x) {
    float e = __expf(2.f * x);
    return 1.f - __fdividef(2.f, e + 1.f);
}

__device__ __forceinline__ void ffma2(ull& d, ull a, ull b) {
    asm("fma.rn.f32x2 %0, %1, %2, %0;" : "+l"(d) : "l"(a), "l"(b));
}
__device__ __forceinline__ float hsum2(ull v) {
    return __int_as_float((unsigned)(v & 0xffffffffull)) + __int_as_float((unsigned)(v >> 32));
}
__device__ __forceinline__ uint32_t smem_to_u32(const void* p) {
    uint32_t a;
    asm("{ .reg .u64 t; cvta.to.shared.u64 t, %1; cvt.u32.u64 %0, t; }" : "=r"(a) : "l"(p));
    return a;
}

#define LDSM_X4(r0, r1, r2, r3, addr) \
    asm volatile("ldmatrix.sync.aligned.m8n8.x4.shared.b16 {%0,%1,%2,%3}, [%4];" \
                 : "=r"(r0), "=r"(r1), "=r"(r2), "=r"(r3) : "r"(addr))

// NOTE: no volatile — pure register op; lets the compiler/ptxas schedule freely.
#define MMA16816(c, a, b0, b1) \
    asm("mma.sync.aligned.m16n8k16.row.col.f32.bf16.bf16.f32 " \
        "{%0,%1,%2,%3},{%4,%5,%6,%7},{%8,%9},{%0,%1,%2,%3};" \
        : "+f"((c)[0]), "+f"((c)[1]), "+f"((c)[2]), "+f"((c)[3]) \
        : "r"((a)[0]), "r"((a)[1]), "r"((a)[2]), "r"((a)[3]), "r"(b0), "r"(b1))

#define MBARRIER_INIT(mb, c) \
    asm volatile("mbarrier.init.shared.b64 [%0], %1;" :: "r"((uint32_t)(mb)), "r"((uint32_t)(c)) : "memory")
#define MBAR_ARRIVE_EXPECT(mb, bytes) \
    asm volatile("mbarrier.arrive.expect_tx.shared.b64 _, [%0], %1;" \
                 :: "r"((uint32_t)(mb)), "r"((uint32_t)(bytes)) : "memory")
#define BULK_G2S(dst, src, bytes, mb) \
    asm volatile("cp.async.bulk.shared::cta.global.mbarrier::complete_tx::bytes [%0], [%1], %2, [%3];" \
                 :: "r"((uint32_t)(dst)), "l"(src), "r"((uint32_t)(bytes)), "r"((uint32_t)(mb)) : "memory")
#define MBARRIER_WAIT_PARITY(mb, ph) do { \
    uint32_t _m = (uint32_t)(mb); uint32_t _p = (uint32_t)(ph); uint32_t _d; \
    asm volatile("{\n\t.reg .pred p;\n\t" \
        "mbarrier.try_wait.parity.acquire.cta.shared::cta.b64 p, [%1], %2;\n\t" \
        "selp.b32 %0, 1, 0, p;\n\t}" : "=r"(_d) : "r"(_m), "r"(_p) : "memory"); \
    if (!_d) { \
        asm volatile("{\n\t.reg .pred P1;\n\t" \
            "WL_%=:\n\t" \
            "mbarrier.try_wait.parity.acquire.cta.shared::cta.b64 P1, [%0], %1, 0x989680;\n\t" \
            "@P1 bra.uni WD_%=;\n\tbra.uni WL_%=;\n\tWD_%=:\n\t}" \
            :: "r"(_m), "r"(_p) : "memory"); \
    } } while (0)

// ---------------- init ----------------------------------------------------------
__global__ void zero_kernel() {
    int i = blockIdx.x * blockDim.x + threadIdx.x;
    if (i < (NCH * 2 * BB * CHK) / 2) ((uint32_t*)g_hpk)[i] = 0u;  // zero sel 0
    if (i < HH) g_kh[i] = 0.f;
    if (i < NBLK) { g_flags[i] = 0u; g_kflags[i] = 0u; }
}

__global__ void pad_kernel() {}

// ---------------- xproj (f32x2 scalar GEMM) --------------------------------------
#define XBM 128
#define XBN 64
#define XBK 20
__global__ void xproj_kernel(const int* __restrict__ x, const float* __restrict__ emb,
                             const float* __restrict__ Wih, const float* __restrict__ bih) {
    __shared__ float As[XBM * XBK];
    __shared__ float Bs[XBN * XBK];
    __shared__ int rid[XBM];

    int tid = threadIdx.x;
    int i0 = blockIdx.y * XBM;
    int g0 = blockIdx.x * XBN;

    if (tid < XBM) {
        int i = i0 + tid;
        int t = i / BB, b = i % BB;
        rid[tid] = x[b * TT + t];
    }
    __syncthreads();

    int tx = tid & 15;
    int ty = tid >> 4;

    ull acc[8][4];
#pragma unroll
    for (int r = 0; r < 8; ++r)
#pragma unroll
        for (int c = 0; c < 4; ++c) acc[r][c] = 0ull;

    for (int k0 = 0; k0 < EE; k0 += XBK) {
        for (int idx = tid; idx < XBM * XBK; idx += 256) {
            int row = idx / XBK, kk = idx % XBK;
            As[row * XBK + kk] = emb[(size_t)rid[row] * EE + k0 + kk];
        }
        for (int idx = tid; idx < XBN * XBK; idx += 256) {
            int c = idx / XBK, kk = idx % XBK;
            Bs[c * XBK + kk] = Wih[(size_t)(g0 + c) * EE + k0 + kk];
        }
        __syncthreads();
#pragma unroll
        for (int kp = 0; kp < XBK / 2; ++kp) {
            ull bv[4];
#pragma unroll
            for (int c = 0; c < 4; ++c)
                bv[c] = *(const ull*)(Bs + (tx * 4 + c) * XBK + 2 * kp);
#pragma unroll
            for (int r = 0; r < 8; ++r) {
                ull av = *(const ull*)(As + (ty * 8 + r) * XBK + 2 * kp);
#pragma unroll
                for (int c = 0; c < 4; ++c) ffma2(acc[r][c], av, bv[c]);
            }
        }
        __syncthreads();
    }
#pragma unroll
    for (int r = 0; r < 8; ++r) {
        size_t i = (size_t)(i0 + ty * 8 + r);
#pragma unroll
        for (int c = 0; c < 4; ++c) {
            int g = g0 + tx * 4 + c;
            g_xproj[i * H3 + g] = hsum2(acc[r][c]) + bih[g];
        }
    }
}

// ---------------- barriers -------------------------------------------------------
__device__ __forceinline__ void grid_barrier(unsigned target) {
    __syncthreads();
    if (threadIdx.x == 0) {
        __threadfence();
        g_flags[blockIdx.x] = target;
    }
    if (threadIdx.x < NBLK) {
        while (g_flags[threadIdx.x] < target) { }
    }
    __syncthreads();
}
__device__ __forceinline__ void kgrid_barrier(unsigned target) {
    __syncthreads();
    if (threadIdx.x == 0) {
        __threadfence();
        g_kflags[blockIdx.x] = target;
    }
    if (threadIdx.x < NBLK) {
        while (g_kflags[threadIdx.x] < target) { }
    }
    __syncthreads();
}

// ---------------- fused key-GRU kernel -------------------------------------------
__global__ void __launch_bounds__(256, 1)
keyall_kernel(const int* __restrict__ key_ids, const float* __restrict__ emb,
              const float* __restrict__ Wih, const float* __restrict__ Whh,
              const float* __restrict__ bih, const float* __restrict__ bhh,
              const float* __restrict__ Wg, const float* __restrict__ bg) {
    extern __shared__ char smem[];
    float* ke    = (float*)(smem + KA_KE);
    float* Wsl   = (float*)(smem + KA_WSL);
    float* kxp_s = (float*)(smem + KA_KXP);
    float* kh_s  = (float*)(smem + KA_KH);
    float* hp_s  = (float*)(smem + KA_HP);

    int tid = threadIdx.x;
    int lane = tid & 31, w = tid >> 5;
    int j0 = blockIdx.x * 8;

    for (int i = tid; i < KEYLEN * EE; i += 256) {
        int t = i / EE, e = i % EE;
        ke[i] = emb[(size_t)key_ids[t] * EE + e];
    }
    for (int i = tid; i < 24 * HH; i += 256) {
        int n = i >> 10, k = i & 1023;
        Wsl[i] = Whh[(size_t)((n >> 3) * HH + j0 + (n & 7)) * HH + k];
    }
    __syncthreads();

    for (int i = tid; i < KEYLEN * 24; i += 256) {
        int t = i / 24, n = i % 24;
        int grow = (n >> 3) * HH + j0 + (n & 7);
        const float* wr = Wih + (size_t)grow * EE;
        float acc = 0.f;
        for (int e = 0; e < EE; ++e) acc += wr[e] * ke[t * EE + e];
        kxp_s[i] = acc + bih[grow];
    }
    __syncthreads();

    for (int t = 0; t < KEYLEN; ++t) {
        for (int i = tid; i < HH; i += 256) kh_s[i] = __ldcg(&g_kh[i]);
        __syncthreads();
#pragma unroll
        for (int rr = 0; rr < 3; ++rr) {
            int n = w * 3 + rr;
            const float* wr = Wsl + n * HH;
            float a = 0.f;
            for (int k = lane; k < HH; k += 32) a += wr[k] * kh_s[k];
#pragma unroll
            for (int o = 16; o; o >>= 1) a += __shfl_xor_sync(0xffffffffu, a, o);
            if (lane == 0) hp_s[n] = a;
        }
        __syncthreads();
        if (tid < 8) {
            int j = j0 + tid;
            float r = sigm(kxp_s[t * 24 + tid] + hp_s[tid] + bhh[j]);
            float z = sigm(kxp_s[t * 24 + 8 + tid] + hp_s[8 + tid] + bhh[HH + j]);
            float n2 = tanh_fast(kxp_s[t * 24 + 16 + tid] + r * (hp_s[16 + tid] + bhh[2 * HH + j]));
            g_kh[j] = (1.f - z) * n2 + z * kh_s[j];
        }
        kgrid_barrier((unsigned)(t + 1));
    }

    for (int i = tid; i < HH; i += 256) kh_s[i] = __ldcg(&g_kh[i]);
    __syncthreads();
    {
        int j = j0 + w;
        const float* wr = Wg + (size_t)j * HH;
        float a = 0.f;
        for (int k = lane; k < HH; k += 32) a += wr[k] * kh_s[k];
#pragma unroll
        for (int o = 16; o; o >>= 1) a += __shfl_xor_sync(0xffffffffu, a, o);
        if (lane == 0) g_gate[j] = sigm(a + bg[j]);
    }
}

// ---------------- persistent HMMA recurrence (latency-hiding MMA schedule) -------
__global__ void __launch_bounds__(RTH, 1)
recur_kernel(const float* __restrict__ Whh, const float* __restrict__ bhh,
             float* __restrict__ out) {
    extern __shared__ char smem[];
    uint32_t smem_base = smem_to_u32(smem);
    float* bias_s = (float*)(smem + SM_BIAS);
    float* gate_s = (float*)(smem + SM_GATE);
    __nv_bfloat16* whi_s = (__nv_bfloat16*)(smem + SM_WHI);
    __nv_bfloat16* wlo_s = (__nv_bfloat16*)(smem + SM_WLO);

    int tid = threadIdx.x;
    int lane = tid & 31;
    int w = tid >> 5;
    int j0 = blockIdx.x * 8;

    if (tid == 0) {
#pragma unroll
        for (int s = 0; s < NSTG; ++s) MBARRIER_INIT(smem_base + SM_MBAR + s * 8, 1);
    }
    asm volatile("fence.proxy.async.shared::cta;" ::: "memory");

    for (int idx = tid; idx < 24 * HH; idx += RTH) {
        int n = idx >> 10, k = idx & (HH - 1);
        float f = Whh[(size_t)((n >> 3) * HH + j0 + (n & 7)) * HH + k];
        __nv_bfloat16 hi = __float2bfloat16_rn(f);
        __nv_bfloat16 lo = __float2bfloat16_rn(f - __bfloat162float(hi));
        whi_s[n * 1032 + k] = hi;
        wlo_s[n * 1032 + k] = lo;
    }
    if (tid < 24) bias_s[tid] = bhh[(tid >> 3) * HH + j0 + (tid & 7)];
    if (tid < 8)  gate_s[tid] = g_gate[j0 + tid];
    __syncthreads();

    // fragment geometry
    int arow = 16 * w + (lane & 15);
    int ar7 = arow & 7;
    uint32_t arowb = (uint32_t)(arow * 128);
    int lhalf = lane >> 4;
    uint32_t b_off[3];
#pragma unroll
    for (int nt = 0; nt < 3; ++nt)
        b_off[nt] = (uint32_t)((nt * 8 + (lane & 7)) * 2064 + (lane >> 3) * 16);

    int row0 = 16 * w + (lane >> 2);
    int jc = 2 * (lane & 3);
    float gv = gate_s[jc], gv1 = gate_s[jc + 1];
    float b_r0 = bias_s[jc],      b_r1 = bias_s[jc + 1];
    float b_z0 = bias_s[8 + jc],  b_z1 = bias_s[8 + jc + 1];
    float b_n0 = bias_s[16 + jc], b_n1 = bias_s[16 + jc + 1];

    int mychunk = j0 >> 6;
    int cw = (j0 & 63) + jc;
    uint32_t ep0 = (uint32_t)(((row0 * 128 + cw * 2) ^ ((row0 & 7) << 4)));
    uint32_t ep1 = (uint32_t)((((row0 + 8) * 128 + cw * 2) ^ (((row0 + 8) & 7) << 4)));

    unsigned phbits = 0;
    int stg = 0;

#pragma unroll 1
    for (int t = 0; t < TT; ++t) {
        int sel = t & 1;
        const char* hsrc = (const char*)&g_hpk[sel][0][0][0][0];
        char* hdst = (char*)&g_hpk[sel ^ 1][0][0][0][0];
        const float* xp = g_xproj + (size_t)t * BB * H3;

        if (tid == 0) {
            int s = stg;
#pragma unroll
            for (int p = 0; p < NSTG; ++p) {
                uint32_t mb = smem_base + SM_MBAR + s * 8;
                MBAR_ARRIVE_EXPECT(mb, CHKB);
                BULK_G2S(smem_base + SM_A + s * CHKB, hsrc + (size_t)p * CHKB, CHKB, mb);
                s = (s + 1 == NSTG) ? 0 : s + 1;
            }
        }

        const float* xpr0 = xp + (size_t)row0 * H3 + j0 + jc;
        const float* xpr1 = xp + (size_t)(row0 + 8) * H3 + j0 + jc;
        float2 xr0 = __ldcs((const float2*)(xpr0));
        float2 xz0 = __ldcs((const float2*)(xpr0 + HH));
        float2 xn0 = __ldcs((const float2*)(xpr0 + 2 * HH));
        float2 xr1 = __ldcs((const float2*)(xpr1));
        float2 xz1 = __ldcs((const float2*)(xpr1 + HH));
        float2 xn1 = __ldcs((const float2*)(xpr1 + 2 * HH));
        const char* hcs = hsrc + (size_t)mychunk * CHKB;
        __nv_bfloat162 hh0 = *(const __nv_bfloat162*)(hcs + ep0);
        __nv_bfloat162 hl0 = *(const __nv_bfloat162*)(hcs + 16384 + ep0);
        __nv_bfloat162 hh1 = *(const __nv_bfloat162*)(hcs + ep1);
        __nv_bfloat162 hl1 = *(const __nv_bfloat162*)(hcs + 16384 + ep1);
        float hold00 = __low2float(hh0) + __low2float(hl0);
        float hold01 = __high2float(hh0) + __high2float(hl0);
        float hold10 = __low2float(hh1) + __low2float(hl1);
        float hold11 = __high2float(hh1) + __high2float(hl1);

        // 6 accumulators: [ntile][k-parity] — breaks same-acc dependency chains
        float cacc[3][2][4];
#pragma unroll
        for (int nt = 0; nt < 3; ++nt)
#pragma unroll
            for (int s = 0; s < 2; ++s)
#pragma unroll
                for (int i = 0; i < 4; ++i) cacc[nt][s][i] = 0.f;

#pragma unroll 1
        for (int c = 0; c < NCH; ++c) {
            uint32_t mb = smem_base + SM_MBAR + stg * 8;
            MBARRIER_WAIT_PARITY(mb, (phbits >> stg) & 1);
            phbits ^= (1u << stg);

            uint32_t sbase = smem_base + SM_A + (uint32_t)(stg * CHKB) + arowb;
#pragma unroll
            for (int s2 = 0; s2 < 2; ++s2) {
                uint32_t bh[3][4], bl[3][4];
#pragma unroll
                for (int nt = 0; nt < 3; ++nt) {
                    uint32_t bb = smem_base + b_off[nt] + (uint32_t)(c * 128 + s2 * 64);
                    LDSM_X4(bh[nt][0], bh[nt][1], bh[nt][2], bh[nt][3], bb + SM_WHI);
                    LDSM_X4(bl[nt][0], bl[nt][1], bl[nt][2], bl[nt][3], bb + SM_WLO);
                }
                // preload A fragments for both k-steps
                uint32_t ah[2][4], al[2][4];
#pragma unroll
                for (int s = 0; s < 2; ++s) {
                    int u = s2 * 4 + s * 2 + lhalf;
                    uint32_t aa = sbase + (uint32_t)(((u ^ ar7)) << 4);
                    LDSM_X4(ah[s][0], ah[s][1], ah[s][2], ah[s][3], aa);
                    LDSM_X4(al[s][0], al[s][1], al[s][2], al[s][3], aa + 16384);
                }
                // 18 MMAs, same-accumulator distance = 6
#pragma unroll
                for (int s = 0; s < 2; ++s)
#pragma unroll
                    for (int nt = 0; nt < 3; ++nt)
                        MMA16816(cacc[nt][s], ah[s], bh[nt][2 * s], bh[nt][2 * s + 1]);
#pragma unroll
                for (int s = 0; s < 2; ++s)
#pragma unroll
                    for (int nt = 0; nt < 3; ++nt)
                        MMA16816(cacc[nt][s], ah[s], bl[nt][2 * s], bl[nt][2 * s + 1]);
#pragma unroll
                for (int s = 0; s < 2; ++s)
#pragma unroll
                    for (int nt = 0; nt < 3; ++nt)
                        MMA16816(cacc[nt][s], al[s], bh[nt][2 * s], bh[nt][2 * s + 1]);
            }
            __syncthreads();

            if (c + NSTG < NCH && tid == 0) {
                MBAR_ARRIVE_EXPECT(mb, CHKB);
                BULK_G2S(smem_base + SM_A + (uint32_t)(stg * CHKB),
                         hsrc + (size_t)(c + NSTG) * CHKB, CHKB, mb);
            }
            stg = (stg + 1 == NSTG) ? 0 : stg + 1;
        }

        // merge k-parity accumulators
        float cfin[3][4];
#pragma unroll
        for (int nt = 0; nt < 3; ++nt)
#pragma unroll
            for (int i = 0; i < 4; ++i) cfin[nt][i] = cacc[nt][0][i] + cacc[nt][1][i];

        char* hcd = hdst + (size_t)mychunk * CHKB;
#pragma unroll
        for (int half = 0; half < 2; ++half) {
            int row = row0 + half * 8;
            int ib = 2 * half;
            float xr_ = half ? xr1.x : xr0.x, xr_1 = half ? xr1.y : xr0.y;
            float xz_ = half ? xz1.x : xz0.x, xz_1 = half ? xz1.y : xz0.y;
            float xn_ = half ? xn1.x : xn0.x, xn_1 = half ? xn1.y : xn0.y;
            float ho0 = half ? hold10 : hold00;
            float ho1 = half ? hold11 : hold01;

            float rg0 = sigm(xr_ + cfin[0][ib] + b_r0);
            float zg0 = sigm(xz_ + cfin[1][ib] + b_z0);
            float ng0 = tanh_fast(xn_ + rg0 * (cfin[2][ib] + b_n0));
            float o0 = gv * ((1.f - zg0) * ng0 + zg0 * ho0);

            float rg1 = sigm(xr_1 + cfin[0][ib + 1] + b_r1);
            float zg1 = sigm(xz_1 + cfin[1][ib + 1] + b_z1);
            float ng1 = tanh_fast(xn_1 + rg1 * (cfin[2][ib + 1] + b_n1));
            float o1 = gv1 * ((1.f - zg1) * ng1 + zg1 * ho1);

            if (t == TT - 1) {
                *(float2*)(out + (size_t)row * HH + j0 + jc) = make_float2(o0, o1);
            } else {
                __nv_bfloat16 h0 = __float2bfloat16_rn(o0);
                __nv_bfloat16 h1 = __float2bfloat16_rn(o1);
                __nv_bfloat162 hv; hv.x = h0; hv.y = h1;
                __nv_bfloat162 lv;
                lv.x = __float2bfloat16_rn(o0 - __bfloat162float(h0));
                lv.y = __float2bfloat16_rn(o1 - __bfloat162float(h1));
                uint32_t ep = half ? ep1 : ep0;
                *(__nv_bfloat162*)(hcd + ep) = hv;
                *(__nv_bfloat162*)(hcd + 16384 + ep) = lv;
            }
        }

        if (t < TT - 1) grid_barrier((unsigned)(t + 1));
    }
}

// ---------------- launch ---------------------------------------------------------
extern "C" void kernel_launch(void* const* d_in, const int* in_sizes, int n_in,
                              void* d_out, int out_size) {
    const int* x        = (const int*)d_in[0];
    const int* key_ids  = (const int*)d_in[1];
    const float* emb    = (const float*)d_in[2];
    const float* W_ih   = (const float*)d_in[3];
    const float* W_hh   = (const float*)d_in[4];
    const float* b_ih   = (const float*)d_in[5];
    const float* b_hh   = (const float*)d_in[6];
    const float* W_g    = (const float*)d_in[7];
    const float* b_g    = (const float*)d_in[8];
    float* out = (float*)d_out;

    cudaFuncSetAttribute(recur_kernel, cudaFuncAttributeMaxDynamicSharedMemorySize, SM_TOTAL);
    cudaFuncSetAttribute(keyall_kernel, cudaFuncAttributeMaxDynamicSharedMemorySize, KA_TOTAL);

    zero_kernel<<<(BB * HH + 255) / 256, 256>>>();                               // 0
    keyall_kernel<<<NBLK, 256, KA_TOTAL>>>(key_ids, emb, W_ih, W_hh,
                                           b_ih, b_hh, W_g, b_g);                // 1
    dim3 xg(H3 / XBN, (BB * TT) / XBM);
    xproj_kernel<<<xg, 256>>>(x, emb, W_ih, b_ih);                               // 2
    pad_kernel<<<1, 32>>>();                                                     // 3
    pad_kernel<<<1, 32>>>();                                                     // 4
    recur_kernel<<<NBLK, RTH, SM_TOTAL>>>(W_hh, b_hh, out);                      // 5
}